// round 1
// baseline (speedup 1.0000x reference)
#include <cuda_runtime.h>
#include <cuda_bf16.h>
#include <cstdint>
#include <cstddef>

// Problem constants
#define Bc 4
#define Dc 256
#define Nc 2048
#define Hc 4
#define HD 64   // head dim

// ---------------------------------------------------------------------------
// Scratch (static device arrays; allocation APIs are forbidden)
// ---------------------------------------------------------------------------
__device__ float g_q[(size_t)Bc * Dc * Nc];
__device__ float g_k[(size_t)Bc * Dc * Nc];
__device__ float g_v[(size_t)Bc * Dc * Nc];
__device__ float g_msg[(size_t)Bc * Dc * Nc];
__device__ float g_message[(size_t)Bc * Dc * Nc];
__device__ float g_h1[(size_t)Bc * 2 * Dc * Nc];
__device__ float g_s[(size_t)Bc * Hc * Nc * Nc];   // 268 MB scores/prob scratch

// ---------------------------------------------------------------------------
// Fast exp: FMA polynomial (avoids MUFU throughput wall: 67M exps in softmax)
// exp(x) = 2^(x*log2e), rounding trick for the integer part, deg-5 Taylor of
// 2^f on f in [-0.5,0.5]. Rel err ~2e-6, far inside the 1e-3 budget.
// ---------------------------------------------------------------------------
__device__ __forceinline__ float fexp(float x) {
    x = fmaxf(x, -87.0f);
    float t  = fmaf(x, 1.4426950408889634f, 12582912.0f);  // + 1.5*2^23
    float fi = t - 12582912.0f;                            // rint(x*log2e)
    float f  = fmaf(x, 1.4426950408889634f, -fi);          // in [-0.5, 0.5]
    float p  = 1.3333558e-3f;
    p = fmaf(p, f, 9.6181291e-3f);
    p = fmaf(p, f, 5.5504109e-2f);
    p = fmaf(p, f, 2.4022651e-1f);
    p = fmaf(p, f, 6.9314718e-1f);
    p = fmaf(p, f, 1.0f);
    int e = (int)fi;
    return p * __int_as_float((e + 127) << 23);
}

// ---------------------------------------------------------------------------
// conv1x1 GEMM: Y[b,o,n] = sum_i W[o,i]*X[b,i,n] + bias[o]  (optional relu)
// X is the virtual concat of X1 (D1 channels) and X2 (D2 channels).
// Tiling: 64x64 C-tile, K-step 16, 16x16 threads, 4x4 per thread.
// grid: (N/64, Dout/64, B)
// ---------------------------------------------------------------------------
__global__ void k_conv1x1(const float* __restrict__ W, const float* __restrict__ bias,
                          const float* __restrict__ X1, const float* __restrict__ X2,
                          float* __restrict__ Y,
                          int Dout, int D1, int D2, int relu)
{
    const int N = Nc;
    const int b  = blockIdx.z;
    const int n0 = blockIdx.x * 64;
    const int o0 = blockIdx.y * 64;
    const int Din = D1 + D2;

    __shared__ float Ws[16][65];   // [kk][o] (padded: conflict-free stores)
    __shared__ float Xs[16][64];   // [kk][n]

    const int tx = threadIdx.x, ty = threadIdx.y;
    const int tid = ty * 16 + tx;

    const float* X1b = X1 + (size_t)b * D1 * N;
    const float* X2b = X2 ? (X2 + (size_t)b * D2 * N) : nullptr;

    float acc[4][4] = {};

    for (int k0 = 0; k0 < Din; k0 += 16) {
        // W tile: Ws[kk][o] = W[(o0+o)*Din + k0+kk]
        {
            int kk = tid & 15;
            int o  = tid >> 4;            // 0..15
            #pragma unroll
            for (int i = 0; i < 4; i++)
                Ws[kk][o + 16 * i] = W[(size_t)(o0 + o + 16 * i) * Din + k0 + kk];
        }
        // X tile: Xs[kk][n] = X[b][k0+kk][n0+n] (from X1 or X2)
        {
            int n   = tid & 63;
            int kk4 = tid >> 6;           // 0..3
            #pragma unroll
            for (int i = 0; i < 4; i++) {
                int kk = kk4 + 4 * i;
                int c  = k0 + kk;
                const float* src = (c < D1) ? (X1b + (size_t)c * N)
                                            : (X2b + (size_t)(c - D1) * N);
                Xs[kk][n] = src[n0 + n];
            }
        }
        __syncthreads();
        #pragma unroll
        for (int kk = 0; kk < 16; kk++) {
            float wv[4], xv[4];
            #pragma unroll
            for (int i = 0; i < 4; i++) wv[i] = Ws[kk][ty * 4 + i];
            #pragma unroll
            for (int j = 0; j < 4; j++) xv[j] = Xs[kk][tx * 4 + j];
            #pragma unroll
            for (int i = 0; i < 4; i++)
                #pragma unroll
                for (int j = 0; j < 4; j++)
                    acc[i][j] = fmaf(wv[i], xv[j], acc[i][j]);
        }
        __syncthreads();
    }

    #pragma unroll
    for (int i = 0; i < 4; i++) {
        int o = o0 + ty * 4 + i;
        float bv = bias[o];
        #pragma unroll
        for (int j = 0; j < 4; j++) {
            float val = acc[i][j] + bv;
            if (relu) val = fmaxf(val, 0.0f);
            Y[((size_t)b * Dout + o) * N + n0 + tx * 4 + j] = val;
        }
    }
}

// ---------------------------------------------------------------------------
// Scores: S[bh,n,m] = (1/8) * sum_dd q[b,dd*4+h,n] * k[b,dd*4+h,m]
// 64x64 tile per block, full dd=64 reduction from smem.
// grid: (Nm/64, Nn/64, B*H), block (16,16)
// ---------------------------------------------------------------------------
__global__ void k_scores(const float* __restrict__ q, const float* __restrict__ k,
                         float* __restrict__ S)
{
    const int bh = blockIdx.z;
    const int b = bh >> 2, h = bh & 3;
    const int m0 = blockIdx.x * 64;
    const int n0 = blockIdx.y * 64;

    __shared__ float Qs[64][64];   // [dd][n]
    __shared__ float Ks[64][64];   // [dd][m]

    const int tx = threadIdx.x, ty = threadIdx.y;
    const int tid = ty * 16 + tx;

    const float* qb = q + (size_t)b * Dc * Nc;
    const float* kb = k + (size_t)b * Dc * Nc;

    {
        int col = tid & 63, r = tid >> 6;   // r: 0..3
        #pragma unroll
        for (int it = 0; it < 16; it++) {
            int dd = r + 4 * it;
            size_t coff = (size_t)(dd * 4 + h) * Nc;
            Qs[dd][col] = qb[coff + n0 + col];
            Ks[dd][col] = kb[coff + m0 + col];
        }
    }
    __syncthreads();

    float acc[4][4] = {};
    #pragma unroll 4
    for (int dd = 0; dd < 64; dd++) {
        float4 qv = *(const float4*)&Qs[dd][ty * 4];
        float4 kv = *(const float4*)&Ks[dd][tx * 4];
        float qa[4] = {qv.x, qv.y, qv.z, qv.w};
        float ka[4] = {kv.x, kv.y, kv.z, kv.w};
        #pragma unroll
        for (int i = 0; i < 4; i++)
            #pragma unroll
            for (int j = 0; j < 4; j++)
                acc[i][j] = fmaf(qa[i], ka[j], acc[i][j]);
    }

    float* Sout = S + ((size_t)bh * Nc + n0) * Nc + m0;
    #pragma unroll
    for (int i = 0; i < 4; i++)
        #pragma unroll
        for (int j = 0; j < 4; j++)
            Sout[(size_t)(ty * 4 + i) * Nc + tx * 4 + j] = acc[i][j] * 0.125f;
}

// ---------------------------------------------------------------------------
// Softmax over m, then * edge[b,n,m]; in-place on S.
// grid: (N, B*H), block 256 (8 values/thread)
// ---------------------------------------------------------------------------
__global__ void k_softmax(float* __restrict__ S, const float* __restrict__ edge)
{
    const int n  = blockIdx.x;
    const int bh = blockIdx.y;
    const int b  = bh >> 2;

    float* row = S + ((size_t)bh * Nc + n) * Nc;
    const float* erow = edge + ((size_t)b * Nc + n) * Nc;
    const int tid = threadIdx.x;

    float vals[8];
    float mx = -1e30f;
    #pragma unroll
    for (int j = 0; j < 8; j++) {
        float s = row[tid + 256 * j];
        vals[j] = s;
        mx = fmaxf(mx, s);
    }

    __shared__ float red[8];
    #pragma unroll
    for (int o = 16; o > 0; o >>= 1) mx = fmaxf(mx, __shfl_xor_sync(0xffffffffu, mx, o));
    if ((tid & 31) == 0) red[tid >> 5] = mx;
    __syncthreads();
    float bm = red[0];
    #pragma unroll
    for (int w = 1; w < 8; w++) bm = fmaxf(bm, red[w]);

    float sum = 0.0f;
    #pragma unroll
    for (int j = 0; j < 8; j++) {
        float e = fexp(vals[j] - bm);
        vals[j] = e;
        sum += e;
    }
    #pragma unroll
    for (int o = 16; o > 0; o >>= 1) sum += __shfl_xor_sync(0xffffffffu, sum, o);
    __syncthreads();   // everyone done reading red (max phase)
    if ((tid & 31) == 0) red[tid >> 5] = sum;
    __syncthreads();
    float Z = 0.0f;
    #pragma unroll
    for (int w = 0; w < 8; w++) Z += red[w];
    float inv = 1.0f / Z;

    #pragma unroll
    for (int j = 0; j < 8; j++)
        row[tid + 256 * j] = vals[j] * inv * erow[tid + 256 * j];
}

// ---------------------------------------------------------------------------
// PV: msg[b, dd*4+h, n] = sum_m P[bh,n,m] * v[b, dd*4+h, m]
// 64(dd) x 64(n) tile per block, m tiled by 32.
// grid: (N/64, B*H), block (16,16)
// ---------------------------------------------------------------------------
__global__ void k_pv(const float* __restrict__ P, const float* __restrict__ v,
                     float* __restrict__ Msg)
{
    const int bh = blockIdx.y;
    const int b = bh >> 2, h = bh & 3;
    const int n0 = blockIdx.x * 64;

    __shared__ float Ps[64][33];   // [n][m]
    __shared__ float Vs[64][33];   // [dd][m]

    const int tx = threadIdx.x, ty = threadIdx.y;
    const int tid = ty * 16 + tx;

    const float* Pb = P + (size_t)bh * Nc * Nc;
    const float* vb = v + (size_t)b * Dc * Nc;

    float acc[4][4] = {};   // [i=dd][j=n]

    for (int m0 = 0; m0 < Nc; m0 += 32) {
        int m = tid & 31, r = tid >> 5;   // r: 0..7
        #pragma unroll
        for (int it = 0; it < 8; it++) {
            int row = r + 8 * it;
            Ps[row][m] = Pb[(size_t)(n0 + row) * Nc + m0 + m];
            Vs[row][m] = vb[(size_t)(row * 4 + h) * Nc + m0 + m];
        }
        __syncthreads();
        #pragma unroll 8
        for (int mm = 0; mm < 32; mm++) {
            float vv[4], pv[4];
            #pragma unroll
            for (int i = 0; i < 4; i++) vv[i] = Vs[ty * 4 + i][mm];
            #pragma unroll
            for (int j = 0; j < 4; j++) pv[j] = Ps[tx * 4 + j][mm];
            #pragma unroll
            for (int i = 0; i < 4; i++)
                #pragma unroll
                for (int j = 0; j < 4; j++)
                    acc[i][j] = fmaf(vv[i], pv[j], acc[i][j]);
        }
        __syncthreads();
    }

    #pragma unroll
    for (int i = 0; i < 4; i++) {
        int c = (ty * 4 + i) * 4 + h;   // channel = dd*H + h
        #pragma unroll
        for (int j = 0; j < 4; j++)
            Msg[((size_t)b * Dc + c) * Nc + n0 + tx * 4 + j] = acc[i][j];
    }
}

// ---------------------------------------------------------------------------
// Launch
// Inputs: x, source, edge, Wq, bq, Wk, bk, Wv, bv, Wm, bm, W1, b1, W2, b2
// ---------------------------------------------------------------------------
extern "C" void kernel_launch(void* const* d_in, const int* in_sizes, int n_in,
                              void* d_out, int out_size)
{
    const float* x    = (const float*)d_in[0];
    const float* src  = (const float*)d_in[1];
    const float* edge = (const float*)d_in[2];
    const float* Wq = (const float*)d_in[3];  const float* bq = (const float*)d_in[4];
    const float* Wk = (const float*)d_in[5];  const float* bk = (const float*)d_in[6];
    const float* Wv = (const float*)d_in[7];  const float* bv = (const float*)d_in[8];
    const float* Wm = (const float*)d_in[9];  const float* bm = (const float*)d_in[10];
    const float* W1 = (const float*)d_in[11]; const float* b1 = (const float*)d_in[12];
    const float* W2 = (const float*)d_in[13]; const float* b2 = (const float*)d_in[14];

    float *q, *k, *v, *msg, *message, *h1, *S;
    cudaGetSymbolAddress((void**)&q,       g_q);
    cudaGetSymbolAddress((void**)&k,       g_k);
    cudaGetSymbolAddress((void**)&v,       g_v);
    cudaGetSymbolAddress((void**)&msg,     g_msg);
    cudaGetSymbolAddress((void**)&message, g_message);
    cudaGetSymbolAddress((void**)&h1,      g_h1);
    cudaGetSymbolAddress((void**)&S,       g_s);

    dim3 blk(16, 16);

    // projections
    k_conv1x1<<<dim3(Nc / 64, Dc / 64, Bc), blk>>>(Wq, bq, x,   nullptr, q, Dc, Dc, 0, 0);
    k_conv1x1<<<dim3(Nc / 64, Dc / 64, Bc), blk>>>(Wk, bk, src, nullptr, k, Dc, Dc, 0, 0);
    k_conv1x1<<<dim3(Nc / 64, Dc / 64, Bc), blk>>>(Wv, bv, src, nullptr, v, Dc, Dc, 0, 0);

    // attention
    k_scores <<<dim3(Nc / 64, Nc / 64, Bc * Hc), blk>>>(q, k, S);
    k_softmax<<<dim3(Nc, Bc * Hc), 256>>>(S, edge);
    k_pv     <<<dim3(Nc / 64, Bc * Hc), blk>>>(S, v, msg);

    // merge heads
    k_conv1x1<<<dim3(Nc / 64, Dc / 64, Bc), blk>>>(Wm, bm, msg, nullptr, message, Dc, Dc, 0, 0);

    // MLP on concat([x, message])
    k_conv1x1<<<dim3(Nc / 64, 2 * Dc / 64, Bc), blk>>>(W1, b1, x, message, h1, 2 * Dc, Dc, Dc, 1);
    k_conv1x1<<<dim3(Nc / 64, Dc / 64, Bc), blk>>>(W2, b2, h1, nullptr, (float*)d_out, Dc, 2 * Dc, 0, 0);
}

// round 3
// speedup vs baseline: 1.1512x; 1.1512x over previous
#include <cuda_runtime.h>
#include <cuda_bf16.h>
#include <cstdint>
#include <cstddef>

// Problem constants
#define Bc 4
#define Dc 256
#define Nc 2048
#define Hc 4
#define HD 64   // head dim

// ---------------------------------------------------------------------------
// Scratch (static device arrays; allocation APIs are forbidden)
// ---------------------------------------------------------------------------
__device__ float g_q[(size_t)Bc * Dc * Nc];
__device__ float g_k[(size_t)Bc * Dc * Nc];
__device__ float g_v[(size_t)Bc * Dc * Nc];
__device__ float g_msg[(size_t)Bc * Dc * Nc];
__device__ float g_message[(size_t)Bc * Dc * Nc];
__device__ float g_h1[(size_t)Bc * 2 * Dc * Nc];

// ---------------------------------------------------------------------------
// Fast exp: FMA polynomial (avoids the MUFU throughput wall)
// ---------------------------------------------------------------------------
__device__ __forceinline__ float fexp(float x) {
    x = fmaxf(x, -87.0f);
    float t  = fmaf(x, 1.4426950408889634f, 12582912.0f);  // + 1.5*2^23
    float fi = t - 12582912.0f;                            // rint(x*log2e)
    float f  = fmaf(x, 1.4426950408889634f, -fi);          // in [-0.5, 0.5]
    float p  = 1.3333558e-3f;
    p = fmaf(p, f, 9.6181291e-3f);
    p = fmaf(p, f, 5.5504109e-2f);
    p = fmaf(p, f, 2.4022651e-1f);
    p = fmaf(p, f, 6.9314718e-1f);
    p = fmaf(p, f, 1.0f);
    int e = (int)fi;
    return p * __int_as_float((e + 127) << 23);
}

// ---------------------------------------------------------------------------
// conv1x1 GEMM: Y[b,o,n] = sum_i W[o,i]*X[b,i,n] + bias[o]  (optional relu)
// X is the virtual concat of X1 (D1 channels) and X2 (D2 channels).
// Tiling: 64(o) x 128(n) C-tile, K-step 16, 256 threads, 4x8 per thread.
// grid: (N/128, Dout/64, B)
// ---------------------------------------------------------------------------
__global__ void __launch_bounds__(256)
k_conv1x1(const float* __restrict__ W, const float* __restrict__ bias,
          const float* __restrict__ X1, const float* __restrict__ X2,
          float* __restrict__ Y,
          int Dout, int D1, int D2, int relu)
{
    const int N = Nc;
    const int b  = blockIdx.z;
    const int n0 = blockIdx.x * 128;
    const int o0 = blockIdx.y * 64;
    const int Din = D1 + D2;

    __shared__ float Ws[16][65];    // [kk][o] (scalar access only; pad ok)
    __shared__ float Xs[16][128];   // [kk][n]

    const int tid = threadIdx.x;
    const int tx = tid & 15, ty = tid >> 4;

    const float* X1b = X1 + (size_t)b * D1 * N;
    const float* X2b = X2 ? (X2 + (size_t)b * D2 * N) : nullptr;

    float acc[4][8] = {};

    for (int k0 = 0; k0 < Din; k0 += 16) {
        {
            int kk = tid & 15;
            int o  = tid >> 4;
            #pragma unroll
            for (int i = 0; i < 4; i++)
                Ws[kk][o + 16 * i] = W[(size_t)(o0 + o + 16 * i) * Din + k0 + kk];
        }
        {
            int n     = tid & 127;
            int khalf = tid >> 7;   // 0..1
            #pragma unroll
            for (int i = 0; i < 8; i++) {
                int kk = khalf * 8 + i;
                int c  = k0 + kk;
                const float* src = (c < D1) ? (X1b + (size_t)c * N)
                                            : (X2b + (size_t)(c - D1) * N);
                Xs[kk][n] = src[n0 + n];
            }
        }
        __syncthreads();
        #pragma unroll 4
        for (int kk = 0; kk < 16; kk++) {
            float w0 = Ws[kk][ty * 4 + 0];
            float w1 = Ws[kk][ty * 4 + 1];
            float w2 = Ws[kk][ty * 4 + 2];
            float w3 = Ws[kk][ty * 4 + 3];
            float4 xa = *(const float4*)&Xs[kk][tx * 4];
            float4 xb = *(const float4*)&Xs[kk][64 + tx * 4];
            float w[4] = {w0, w1, w2, w3};
            float x8[8] = {xa.x, xa.y, xa.z, xa.w, xb.x, xb.y, xb.z, xb.w};
            #pragma unroll
            for (int i = 0; i < 4; i++)
                #pragma unroll
                for (int j = 0; j < 8; j++)
                    acc[i][j] = fmaf(w[i], x8[j], acc[i][j]);
        }
        __syncthreads();
    }

    #pragma unroll
    for (int i = 0; i < 4; i++) {
        int o = o0 + ty * 4 + i;
        float bv = bias[o];
        float4 ra, rb;
        ra.x = acc[i][0] + bv; ra.y = acc[i][1] + bv;
        ra.z = acc[i][2] + bv; ra.w = acc[i][3] + bv;
        rb.x = acc[i][4] + bv; rb.y = acc[i][5] + bv;
        rb.z = acc[i][6] + bv; rb.w = acc[i][7] + bv;
        if (relu) {
            ra.x = fmaxf(ra.x, 0.f); ra.y = fmaxf(ra.y, 0.f);
            ra.z = fmaxf(ra.z, 0.f); ra.w = fmaxf(ra.w, 0.f);
            rb.x = fmaxf(rb.x, 0.f); rb.y = fmaxf(rb.y, 0.f);
            rb.z = fmaxf(rb.z, 0.f); rb.w = fmaxf(rb.w, 0.f);
        }
        float* yrow = Y + ((size_t)b * Dout + o) * N + n0;
        *(float4*)&yrow[tx * 4]      = ra;
        *(float4*)&yrow[64 + tx * 4] = rb;
    }
}

// ---------------------------------------------------------------------------
// Fused flash attention with edge weighting.   48KB static smem total.
//   S[n,m]   = (1/8) sum_dd q[dd,n] k[dd,m]
//   P        = softmax_m(S) * edge[n,m]     (Z excludes edge, matching ref)
//   msg[dd,n]= sum_m P[n,m] v[dd,m]
// One block = one (b,h) x 64-row n-tile; loops over 32 m-tiles of 64.
// KV buffer is shared between the K tile (S GEMM) and the V tile (PV GEMM);
// V is stored transposed with an XOR swizzle so both its scalar stores and
// its LDS.128 reads are (near) conflict-free on an unpadded 64-stride.
// grid: (N/64, B*H), block 256
// ---------------------------------------------------------------------------
__device__ __forceinline__ int vswz(int m, int dd) {
    return m * 64 + (dd ^ ((m & 15) << 2));
}

__global__ void __launch_bounds__(256)
k_flash(const float* __restrict__ q, const float* __restrict__ k,
        const float* __restrict__ v, const float* __restrict__ edge,
        float* __restrict__ Msg)
{
    const int bh = blockIdx.y;
    const int b = bh >> 2, h = bh & 3;
    const int n0 = blockIdx.x * 64;

    __shared__ float Qs[64 * 64];   // [dd][n]
    __shared__ float KV[64 * 64];   // K: [dd][m]; later V: swizzled [m][dd]
    __shared__ float Ps[64 * 64];   // [n][m]; reused as O[dd][n] in epilogue

    const int tid = threadIdx.x;
    const int tx = tid & 15, ty = tid >> 4;
    const int col = tid & 63, r = tid >> 6;   // loader mapping (r: 0..3)

    const float* qb = q + (size_t)b * Dc * Nc;
    const float* kb = k + (size_t)b * Dc * Nc;
    const float* vb = v + (size_t)b * Dc * Nc;

    // Load Q tile once: Qs[dd][n]
    #pragma unroll
    for (int it = 0; it < 16; it++) {
        int dd = r + 4 * it;
        Qs[dd * 64 + col] = qb[(size_t)(dd * 4 + h) * Nc + n0 + col];
    }

    float acc_o[4][4] = {};
    float mx[4] = {-1e30f, -1e30f, -1e30f, -1e30f};
    float Z[4]  = {};

    for (int m0 = 0; m0 < Nc; m0 += 64) {
        // Prefetch edge tile for this thread's 4x4 (consumed in softmax)
        float4 ev[4];
        #pragma unroll
        for (int i = 0; i < 4; i++)
            ev[i] = *(const float4*)&edge[((size_t)b * Nc + n0 + ty * 4 + i) * Nc
                                          + m0 + tx * 4];

        // K tile into KV (prev iteration fully drained by loop-bottom sync)
        #pragma unroll
        for (int it = 0; it < 16; it++) {
            int dd = r + 4 * it;
            KV[dd * 64 + col] = kb[(size_t)(dd * 4 + h) * Nc + m0 + col];
        }
        __syncthreads();   // K (and first-iter Q) visible

        // S = Q^T K  (64x64x64)
        float s[4][4] = {};
        #pragma unroll 4
        for (int kk0 = 0; kk0 < 64; kk0 += 4) {
            float qa[4][4], ka[4][4];
            #pragma unroll
            for (int u = 0; u < 4; u++) {
                float4 t = *(const float4*)&Qs[(kk0 + u) * 64 + ty * 4];
                qa[u][0] = t.x; qa[u][1] = t.y; qa[u][2] = t.z; qa[u][3] = t.w;
                float4 r4 = *(const float4*)&KV[(kk0 + u) * 64 + tx * 4];
                ka[u][0] = r4.x; ka[u][1] = r4.y; ka[u][2] = r4.z; ka[u][3] = r4.w;
            }
            #pragma unroll
            for (int u = 0; u < 4; u++)
                #pragma unroll
                for (int i = 0; i < 4; i++)
                    #pragma unroll
                    for (int j = 0; j < 4; j++)
                        s[i][j] = fmaf(qa[u][i], ka[u][j], s[i][j]);
        }

        // Issue V global loads now (registers); latency hidden under softmax
        float vr[16];
        #pragma unroll
        for (int it = 0; it < 16; it++) {
            int dd = r + 4 * it;
            vr[it] = vb[(size_t)(dd * 4 + h) * Nc + m0 + col];
        }

        // Online softmax per row (row n = ty*4+i spans the 16 tx lanes,
        // which form one half-warp -> shuffle offsets 8..1 stay inside it)
        #pragma unroll
        for (int i = 0; i < 4; i++) {
            float s0 = s[i][0] * 0.125f, s1 = s[i][1] * 0.125f;
            float s2 = s[i][2] * 0.125f, s3 = s[i][3] * 0.125f;
            float tm = fmaxf(fmaxf(s0, s1), fmaxf(s2, s3));
            #pragma unroll
            for (int o = 8; o > 0; o >>= 1)
                tm = fmaxf(tm, __shfl_xor_sync(0xffffffffu, tm, o));
            float nm = fmaxf(mx[i], tm);
            float c  = fexp(mx[i] - nm);
            mx[i] = nm;
            float p0 = fexp(s0 - nm), p1 = fexp(s1 - nm);
            float p2 = fexp(s2 - nm), p3 = fexp(s3 - nm);
            float ts = (p0 + p1) + (p2 + p3);
            #pragma unroll
            for (int o = 8; o > 0; o >>= 1)
                ts += __shfl_xor_sync(0xffffffffu, ts, o);
            Z[i] = Z[i] * c + ts;
            acc_o[i][0] *= c; acc_o[i][1] *= c;
            acc_o[i][2] *= c; acc_o[i][3] *= c;
            float4 pe;
            pe.x = p0 * ev[i].x; pe.y = p1 * ev[i].y;
            pe.z = p2 * ev[i].z; pe.w = p3 * ev[i].w;
            *(float4*)&Ps[(ty * 4 + i) * 64 + tx * 4] = pe;
        }
        __syncthreads();   // all S-GEMM reads of KV done; Ps complete

        // V tile into KV, transposed + swizzled: KV[vswz(m, dd)] = v[dd][m]
        #pragma unroll
        for (int it = 0; it < 16; it++) {
            int dd = r + 4 * it;
            KV[vswz(col, dd)] = vr[it];
        }
        __syncthreads();   // V visible

        // acc_o[n][d] += P[n][m] * V[m][d]
        #pragma unroll 4
        for (int mm0 = 0; mm0 < 64; mm0 += 4) {
            float pa[4][4], va[4][4];
            #pragma unroll
            for (int i = 0; i < 4; i++) {
                float4 t = *(const float4*)&Ps[(ty * 4 + i) * 64 + mm0];
                pa[i][0] = t.x; pa[i][1] = t.y; pa[i][2] = t.z; pa[i][3] = t.w;
            }
            #pragma unroll
            for (int u = 0; u < 4; u++) {
                float4 t = *(const float4*)&KV[vswz(mm0 + u, tx * 4)];
                va[u][0] = t.x; va[u][1] = t.y; va[u][2] = t.z; va[u][3] = t.w;
            }
            #pragma unroll
            for (int i = 0; i < 4; i++)
                #pragma unroll
                for (int u = 0; u < 4; u++)
                    #pragma unroll
                    for (int j = 0; j < 4; j++)
                        acc_o[i][j] = fmaf(pa[i][u], va[u][j], acc_o[i][j]);
        }
        __syncthreads();   // drain KV/Ps reads before next iteration's stores
    }

    // Epilogue: normalize, transpose via smem (reuse Ps as O[dd][n])
    #pragma unroll
    for (int i = 0; i < 4; i++) {
        float inv = 1.0f / Z[i];
        #pragma unroll
        for (int j = 0; j < 4; j++)
            Ps[(tx * 4 + j) * 64 + ty * 4 + i] = acc_o[i][j] * inv;
    }
    __syncthreads();
    #pragma unroll
    for (int it = 0; it < 16; it++) {
        int dd = r + 4 * it;
        Msg[((size_t)b * Dc + dd * 4 + h) * Nc + n0 + col] = Ps[dd * 64 + col];
    }
}

// ---------------------------------------------------------------------------
// Launch
// Inputs: x, source, edge, Wq, bq, Wk, bk, Wv, bv, Wm, bm, W1, b1, W2, b2
// ---------------------------------------------------------------------------
extern "C" void kernel_launch(void* const* d_in, const int* in_sizes, int n_in,
                              void* d_out, int out_size)
{
    const float* x    = (const float*)d_in[0];
    const float* src  = (const float*)d_in[1];
    const float* edge = (const float*)d_in[2];
    const float* Wq = (const float*)d_in[3];  const float* bq = (const float*)d_in[4];
    const float* Wk = (const float*)d_in[5];  const float* bk = (const float*)d_in[6];
    const float* Wv = (const float*)d_in[7];  const float* bv = (const float*)d_in[8];
    const float* Wm = (const float*)d_in[9];  const float* bm = (const float*)d_in[10];
    const float* W1 = (const float*)d_in[11]; const float* b1 = (const float*)d_in[12];
    const float* W2 = (const float*)d_in[13]; const float* b2 = (const float*)d_in[14];

    float *q, *k, *v, *msg, *message, *h1;
    cudaGetSymbolAddress((void**)&q,       g_q);
    cudaGetSymbolAddress((void**)&k,       g_k);
    cudaGetSymbolAddress((void**)&v,       g_v);
    cudaGetSymbolAddress((void**)&msg,     g_msg);
    cudaGetSymbolAddress((void**)&message, g_message);
    cudaGetSymbolAddress((void**)&h1,      g_h1);

    // projections: 64o x 128n tiles
    k_conv1x1<<<dim3(Nc / 128, Dc / 64, Bc), 256>>>(Wq, bq, x,   nullptr, q, Dc, Dc, 0, 0);
    k_conv1x1<<<dim3(Nc / 128, Dc / 64, Bc), 256>>>(Wk, bk, src, nullptr, k, Dc, Dc, 0, 0);
    k_conv1x1<<<dim3(Nc / 128, Dc / 64, Bc), 256>>>(Wv, bv, src, nullptr, v, Dc, Dc, 0, 0);

    // fused attention (scores + softmax*edge + PV)
    k_flash<<<dim3(Nc / 64, Bc * Hc), 256>>>(q, k, v, edge, msg);

    // merge heads
    k_conv1x1<<<dim3(Nc / 128, Dc / 64, Bc), 256>>>(Wm, bm, msg, nullptr, message, Dc, Dc, 0, 0);

    // MLP on concat([x, message])
    k_conv1x1<<<dim3(Nc / 128, 2 * Dc / 64, Bc), 256>>>(W1, b1, x, message, h1, 2 * Dc, Dc, Dc, 1);
    k_conv1x1<<<dim3(Nc / 128, Dc / 64, Bc), 256>>>(W2, b2, h1, nullptr, (float*)d_out, Dc, 2 * Dc, 0, 0);
}

// round 4
// speedup vs baseline: 1.4823x; 1.2876x over previous
#include <cuda_runtime.h>
#include <cuda_bf16.h>
#include <cstdint>
#include <cstddef>

// Problem constants
#define Bc 4
#define Dc 256
#define Nc 2048
#define Hc 4
#define HD 64   // head dim

// ---------------------------------------------------------------------------
// Scratch (static device arrays; allocation APIs are forbidden)
// ---------------------------------------------------------------------------
__device__ float g_q[(size_t)Bc * Dc * Nc];
__device__ float g_k[(size_t)Bc * Dc * Nc];
__device__ float g_v[(size_t)Bc * Dc * Nc];
__device__ float g_msg[(size_t)Bc * Dc * Nc];
__device__ float g_message[(size_t)Bc * Dc * Nc];
__device__ float g_h1[(size_t)Bc * 2 * Dc * Nc];

// ---------------------------------------------------------------------------
// Fast exp: FMA polynomial (avoids the MUFU throughput wall)
// ---------------------------------------------------------------------------
__device__ __forceinline__ float fexp(float x) {
    x = fmaxf(x, -87.0f);
    float t  = fmaf(x, 1.4426950408889634f, 12582912.0f);
    float fi = t - 12582912.0f;
    float f  = fmaf(x, 1.4426950408889634f, -fi);
    float p  = 1.3333558e-3f;
    p = fmaf(p, f, 9.6181291e-3f);
    p = fmaf(p, f, 5.5504109e-2f);
    p = fmaf(p, f, 2.4022651e-1f);
    p = fmaf(p, f, 6.9314718e-1f);
    p = fmaf(p, f, 1.0f);
    int e = (int)fi;
    return p * __int_as_float((e + 127) << 23);
}

// ---------------------------------------------------------------------------
// Tensor-core helpers: tf32 m16n8k8 mma + round-to-tf32 convert
// ---------------------------------------------------------------------------
__device__ __forceinline__ uint32_t f2tf(float x) {
    uint32_t r;
    asm("cvt.rna.tf32.f32 %0, %1;" : "=r"(r) : "f"(x));
    return r;
}
__device__ __forceinline__ float f2tf_f(float x) {
    return __uint_as_float(f2tf(x));
}
__device__ __forceinline__ void mma_tf32(float (&d)[4], const uint32_t (&a)[4],
                                         uint32_t b0, uint32_t b1) {
    asm volatile(
        "mma.sync.aligned.m16n8k8.row.col.f32.tf32.tf32.f32 "
        "{%0,%1,%2,%3}, {%4,%5,%6,%7}, {%8,%9}, {%0,%1,%2,%3};\n"
        : "+f"(d[0]), "+f"(d[1]), "+f"(d[2]), "+f"(d[3])
        : "r"(a[0]), "r"(a[1]), "r"(a[2]), "r"(a[3]), "r"(b0), "r"(b1));
}

// ---------------------------------------------------------------------------
// conv1x1 GEMM (unchanged from round 3): 64o x 128n tiles, fp32 FMA
// ---------------------------------------------------------------------------
__global__ void __launch_bounds__(256)
k_conv1x1(const float* __restrict__ W, const float* __restrict__ bias,
          const float* __restrict__ X1, const float* __restrict__ X2,
          float* __restrict__ Y,
          int Dout, int D1, int D2, int relu)
{
    const int N = Nc;
    const int b  = blockIdx.z;
    const int n0 = blockIdx.x * 128;
    const int o0 = blockIdx.y * 64;
    const int Din = D1 + D2;

    __shared__ float Ws[16][65];
    __shared__ float Xs[16][128];

    const int tid = threadIdx.x;
    const int tx = tid & 15, ty = tid >> 4;

    const float* X1b = X1 + (size_t)b * D1 * N;
    const float* X2b = X2 ? (X2 + (size_t)b * D2 * N) : nullptr;

    float acc[4][8] = {};

    for (int k0 = 0; k0 < Din; k0 += 16) {
        {
            int kk = tid & 15;
            int o  = tid >> 4;
            #pragma unroll
            for (int i = 0; i < 4; i++)
                Ws[kk][o + 16 * i] = W[(size_t)(o0 + o + 16 * i) * Din + k0 + kk];
        }
        {
            int n     = tid & 127;
            int khalf = tid >> 7;
            #pragma unroll
            for (int i = 0; i < 8; i++) {
                int kk = khalf * 8 + i;
                int c  = k0 + kk;
                const float* src = (c < D1) ? (X1b + (size_t)c * N)
                                            : (X2b + (size_t)(c - D1) * N);
                Xs[kk][n] = src[n0 + n];
            }
        }
        __syncthreads();
        #pragma unroll 4
        for (int kk = 0; kk < 16; kk++) {
            float w0 = Ws[kk][ty * 4 + 0];
            float w1 = Ws[kk][ty * 4 + 1];
            float w2 = Ws[kk][ty * 4 + 2];
            float w3 = Ws[kk][ty * 4 + 3];
            float4 xa = *(const float4*)&Xs[kk][tx * 4];
            float4 xb = *(const float4*)&Xs[kk][64 + tx * 4];
            float w[4] = {w0, w1, w2, w3};
            float x8[8] = {xa.x, xa.y, xa.z, xa.w, xb.x, xb.y, xb.z, xb.w};
            #pragma unroll
            for (int i = 0; i < 4; i++)
                #pragma unroll
                for (int j = 0; j < 8; j++)
                    acc[i][j] = fmaf(w[i], x8[j], acc[i][j]);
        }
        __syncthreads();
    }

    #pragma unroll
    for (int i = 0; i < 4; i++) {
        int o = o0 + ty * 4 + i;
        float bv = bias[o];
        float4 ra, rb;
        ra.x = acc[i][0] + bv; ra.y = acc[i][1] + bv;
        ra.z = acc[i][2] + bv; ra.w = acc[i][3] + bv;
        rb.x = acc[i][4] + bv; rb.y = acc[i][5] + bv;
        rb.z = acc[i][6] + bv; rb.w = acc[i][7] + bv;
        if (relu) {
            ra.x = fmaxf(ra.x, 0.f); ra.y = fmaxf(ra.y, 0.f);
            ra.z = fmaxf(ra.z, 0.f); ra.w = fmaxf(ra.w, 0.f);
            rb.x = fmaxf(rb.x, 0.f); rb.y = fmaxf(rb.y, 0.f);
            rb.z = fmaxf(rb.z, 0.f); rb.w = fmaxf(rb.w, 0.f);
        }
        float* yrow = Y + ((size_t)b * Dout + o) * N + n0;
        *(float4*)&yrow[tx * 4]      = ra;
        *(float4*)&yrow[64 + tx * 4] = rb;
    }
}

// ---------------------------------------------------------------------------
// Fused flash attention on tensor cores (tf32 mma.sync m16n8k8).
//   S[n,m] = (1/8) sum_dd Q[dd,n] K[dd,m]          (S via A=Q^T regs, B=K smem)
//   P      = softmax_m(S) * edge
//   O^T    : msg[dd,n] = sum_m V[dd,m] P[n,m]      (A=V smem, B=P^T smem)
// 4 warps / 128 threads. Warp w owns n-rows [16w,16w+16) for S+softmax, and
// dd-rows [16w,16w+16) for PV. P crosses warps through smem (one sync).
// Smem: Ks, Vs (natural [dd][m], stride 72), Ps ([n][m], stride 72), cs/zs.
// grid: (N/64, B*H)
// ---------------------------------------------------------------------------
#define KVS 72
#define FLASH_SMEM_FLOATS (3 * 64 * KVS + 128)
#define FLASH_SMEM_BYTES (FLASH_SMEM_FLOATS * 4)

__global__ void __launch_bounds__(128)
k_flash(const float* __restrict__ q, const float* __restrict__ k,
        const float* __restrict__ v, const float* __restrict__ edge,
        float* __restrict__ Msg)
{
    extern __shared__ float sm[];
    float* Ks = sm;                  // [64][KVS]
    float* Vs = sm + 64 * KVS;       // [64][KVS]
    float* Ps = sm + 2 * 64 * KVS;   // [64][KVS]
    float* cs = sm + 3 * 64 * KVS;   // [64] per-tile rescale factors
    float* zs = cs + 64;             // [64] 1/Z at epilogue

    const int bh = blockIdx.y;
    const int b = bh >> 2, h = bh & 3;
    const int n0 = blockIdx.x * 64;

    const int tid  = threadIdx.x;
    const int warp = tid >> 5;
    const int lane = tid & 31;
    const int g  = lane >> 2;    // mma groupID (0..7)
    const int tc = lane & 3;     // mma threadID_in_group
    const int nw = warp * 16;    // this warp's n-strip (S/softmax)
    const int wd = warp * 16;    // this warp's dd-strip (PV output)

    const int lcol = tid & 63;   // K/V loader: column (m)
    const int lr   = tid >> 6;   // K/V loader: row parity (0..1)

    const float* qb = q + (size_t)b * Dc * Nc;
    const float* kb = k + (size_t)b * Dc * Nc;
    const float* vb = v + (size_t)b * Dc * Nc;

    // --- Q a-fragments (A row-major [n][dd]), resident for whole block ---
    uint32_t qa[8][4];
    #pragma unroll
    for (int kk = 0; kk < 8; kk++) {
        int ch0 = (8 * kk + tc) * 4 + h;
        int ch1 = (8 * kk + tc + 4) * 4 + h;
        qa[kk][0] = f2tf(qb[(size_t)ch0 * Nc + n0 + nw + g]);
        qa[kk][1] = f2tf(qb[(size_t)ch0 * Nc + n0 + nw + g + 8]);
        qa[kk][2] = f2tf(qb[(size_t)ch1 * Nc + n0 + nw + g]);
        qa[kk][3] = f2tf(qb[(size_t)ch1 * Nc + n0 + nw + g + 8]);
    }

    float o[8][4] = {};   // O^T d-frags: rows dd (wd+g, wd+g+8), cols n (8j+2tc,+1)
    float mx0 = -1e30f, mx1 = -1e30f, Z0 = 0.f, Z1 = 0.f;

    const float* erow0 = edge + ((size_t)b * Nc + n0 + nw + g) * Nc + 2 * tc;
    const float* erow1 = erow0 + (size_t)8 * Nc;

    for (int m0 = 0; m0 < Nc; m0 += 64) {
        // --- load K and V tiles (coalesced, natural [dd][m], tf32-rounded) ---
        #pragma unroll 8
        for (int it = 0; it < 32; it++) {
            int dd = 2 * it + lr;
            size_t goff = (size_t)(dd * 4 + h) * Nc + m0 + lcol;
            Ks[dd * KVS + lcol] = f2tf_f(kb[goff]);
            Vs[dd * KVS + lcol] = f2tf_f(vb[goff]);
        }
        // --- edge prefetch for this thread's P elements ---
        float2 e0[8], e1[8];
        #pragma unroll
        for (int j = 0; j < 8; j++) {
            e0[j] = *(const float2*)&erow0[m0 + 8 * j];
            e1[j] = *(const float2*)&erow1[m0 + 8 * j];
        }
        __syncthreads();

        // --- S = Q^T K on tensor cores ---
        float s[8][4] = {};
        #pragma unroll
        for (int kk = 0; kk < 8; kk++) {
            const float* kr0 = &Ks[(8 * kk + tc) * KVS + g];
            const float* kr1 = &Ks[(8 * kk + tc + 4) * KVS + g];
            #pragma unroll
            for (int j = 0; j < 8; j++) {
                uint32_t b0 = __float_as_uint(kr0[8 * j]);
                uint32_t b1 = __float_as_uint(kr1[8 * j]);
                mma_tf32(s[j], qa[kk], b0, b1);
            }
        }

        // --- online softmax (rows nw+g and nw+g+8; quad = lanes with same g) ---
        {
            // row 0
            float tm = -1e30f;
            #pragma unroll
            for (int j = 0; j < 8; j++)
                tm = fmaxf(tm, fmaxf(s[j][0], s[j][1]));
            tm *= 0.125f;
            tm = fmaxf(tm, __shfl_xor_sync(0xffffffffu, tm, 1));
            tm = fmaxf(tm, __shfl_xor_sync(0xffffffffu, tm, 2));
            float nm = fmaxf(mx0, tm);
            float c0 = fexp(mx0 - nm);
            mx0 = nm;
            float ts = 0.f;
            #pragma unroll
            for (int j = 0; j < 8; j++) {
                float p0 = fexp(fmaf(s[j][0], 0.125f, -nm));
                float p1 = fexp(fmaf(s[j][1], 0.125f, -nm));
                ts += p0 + p1;
                float2 pe = make_float2(f2tf_f(p0 * e0[j].x), f2tf_f(p1 * e0[j].y));
                *(float2*)&Ps[(nw + g) * KVS + 8 * j + 2 * tc] = pe;
            }
            ts += __shfl_xor_sync(0xffffffffu, ts, 1);
            ts += __shfl_xor_sync(0xffffffffu, ts, 2);
            Z0 = Z0 * c0 + ts;
            if (tc == 0) cs[nw + g] = c0;

            // row 1
            tm = -1e30f;
            #pragma unroll
            for (int j = 0; j < 8; j++)
                tm = fmaxf(tm, fmaxf(s[j][2], s[j][3]));
            tm *= 0.125f;
            tm = fmaxf(tm, __shfl_xor_sync(0xffffffffu, tm, 1));
            tm = fmaxf(tm, __shfl_xor_sync(0xffffffffu, tm, 2));
            nm = fmaxf(mx1, tm);
            float c1 = fexp(mx1 - nm);
            mx1 = nm;
            ts = 0.f;
            #pragma unroll
            for (int j = 0; j < 8; j++) {
                float p0 = fexp(fmaf(s[j][2], 0.125f, -nm));
                float p1 = fexp(fmaf(s[j][3], 0.125f, -nm));
                ts += p0 + p1;
                float2 pe = make_float2(f2tf_f(p0 * e1[j].x), f2tf_f(p1 * e1[j].y));
                *(float2*)&Ps[(nw + g + 8) * KVS + 8 * j + 2 * tc] = pe;
            }
            ts += __shfl_xor_sync(0xffffffffu, ts, 1);
            ts += __shfl_xor_sync(0xffffffffu, ts, 2);
            Z1 = Z1 * c1 + ts;
            if (tc == 0) cs[nw + g + 8] = c1;
        }
        __syncthreads();   // Ps + cs visible to all warps

        // --- rescale O accumulators by per-n factors ---
        #pragma unroll
        for (int j = 0; j < 8; j++) {
            float cA = cs[8 * j + 2 * tc];
            float cB = cs[8 * j + 2 * tc + 1];
            o[j][0] *= cA; o[j][1] *= cB;
            o[j][2] *= cA; o[j][3] *= cB;
        }

        // --- O^T += V * P^T on tensor cores (A=V [dd][m], B=P^T) ---
        #pragma unroll
        for (int kk = 0; kk < 8; kk++) {
            uint32_t av[4];
            av[0] = __float_as_uint(Vs[(wd + g) * KVS + 8 * kk + tc]);
            av[1] = __float_as_uint(Vs[(wd + g + 8) * KVS + 8 * kk + tc]);
            av[2] = __float_as_uint(Vs[(wd + g) * KVS + 8 * kk + tc + 4]);
            av[3] = __float_as_uint(Vs[(wd + g + 8) * KVS + 8 * kk + tc + 4]);
            #pragma unroll
            for (int j = 0; j < 8; j++) {
                uint32_t b0 = __float_as_uint(Ps[(8 * j + g) * KVS + 8 * kk + tc]);
                uint32_t b1 = __float_as_uint(Ps[(8 * j + g) * KVS + 8 * kk + tc + 4]);
                mma_tf32(o[j], av, b0, b1);
            }
        }
        __syncthreads();   // all reads done before next tile's stores
    }

    // --- epilogue: publish 1/Z, then write O^T/Z directly ---
    if (tc == 0) {
        zs[nw + g]     = 1.0f / Z0;
        zs[nw + g + 8] = 1.0f / Z1;
    }
    __syncthreads();

    #pragma unroll
    for (int j = 0; j < 8; j++) {
        float zi0 = zs[8 * j + 2 * tc];
        float zi1 = zs[8 * j + 2 * tc + 1];
        int ch0 = (wd + g) * 4 + h;
        int ch1 = (wd + g + 8) * 4 + h;
        float2 w0 = make_float2(o[j][0] * zi0, o[j][1] * zi1);
        float2 w1 = make_float2(o[j][2] * zi0, o[j][3] * zi1);
        *(float2*)&Msg[((size_t)b * Dc + ch0) * Nc + n0 + 8 * j + 2 * tc] = w0;
        *(float2*)&Msg[((size_t)b * Dc + ch1) * Nc + n0 + 8 * j + 2 * tc] = w1;
    }
}

// ---------------------------------------------------------------------------
// Launch
// ---------------------------------------------------------------------------
extern "C" void kernel_launch(void* const* d_in, const int* in_sizes, int n_in,
                              void* d_out, int out_size)
{
    const float* x    = (const float*)d_in[0];
    const float* src  = (const float*)d_in[1];
    const float* edge = (const float*)d_in[2];
    const float* Wq = (const float*)d_in[3];  const float* bq = (const float*)d_in[4];
    const float* Wk = (const float*)d_in[5];  const float* bk = (const float*)d_in[6];
    const float* Wv = (const float*)d_in[7];  const float* bv = (const float*)d_in[8];
    const float* Wm = (const float*)d_in[9];  const float* bm = (const float*)d_in[10];
    const float* W1 = (const float*)d_in[11]; const float* b1 = (const float*)d_in[12];
    const float* W2 = (const float*)d_in[13]; const float* b2 = (const float*)d_in[14];

    float *q, *k, *v, *msg, *message, *h1;
    cudaGetSymbolAddress((void**)&q,       g_q);
    cudaGetSymbolAddress((void**)&k,       g_k);
    cudaGetSymbolAddress((void**)&v,       g_v);
    cudaGetSymbolAddress((void**)&msg,     g_msg);
    cudaGetSymbolAddress((void**)&message, g_message);
    cudaGetSymbolAddress((void**)&h1,      g_h1);

    // allow >48KB dynamic smem for the flash kernel (attr set, not an alloc)
    cudaFuncSetAttribute(k_flash, cudaFuncAttributeMaxDynamicSharedMemorySize,
                         FLASH_SMEM_BYTES);

    // projections
    k_conv1x1<<<dim3(Nc / 128, Dc / 64, Bc), 256>>>(Wq, bq, x,   nullptr, q, Dc, Dc, 0, 0);
    k_conv1x1<<<dim3(Nc / 128, Dc / 64, Bc), 256>>>(Wk, bk, src, nullptr, k, Dc, Dc, 0, 0);
    k_conv1x1<<<dim3(Nc / 128, Dc / 64, Bc), 256>>>(Wv, bv, src, nullptr, v, Dc, Dc, 0, 0);

    // fused attention on tensor cores
    k_flash<<<dim3(Nc / 64, Bc * Hc), 128, FLASH_SMEM_BYTES>>>(q, k, v, edge, msg);

    // merge heads
    k_conv1x1<<<dim3(Nc / 128, Dc / 64, Bc), 256>>>(Wm, bm, msg, nullptr, message, Dc, Dc, 0, 0);

    // MLP on concat([x, message])
    k_conv1x1<<<dim3(Nc / 128, 2 * Dc / 64, Bc), 256>>>(W1, b1, x, message, h1, 2 * Dc, Dc, Dc, 1);
    k_conv1x1<<<dim3(Nc / 128, Dc / 64, Bc), 256>>>(W2, b2, h1, nullptr, (float*)d_out, Dc, 2 * Dc, 0, 0);
}

// round 5
// speedup vs baseline: 1.9465x; 1.3132x over previous
#include <cuda_runtime.h>
#include <cuda_bf16.h>
#include <cstdint>
#include <cstddef>

// Problem constants
#define Bc 4
#define Dc 256
#define Nc 2048
#define Hc 4
#define HD 64   // head dim

// ---------------------------------------------------------------------------
// Scratch (static device arrays; allocation APIs are forbidden)
// ---------------------------------------------------------------------------
__device__ float g_q[(size_t)Bc * Dc * Nc];
__device__ float g_k[(size_t)Bc * Dc * Nc];
__device__ float g_v[(size_t)Bc * Dc * Nc];
__device__ float g_msg[(size_t)Bc * Dc * Nc];
__device__ float g_message[(size_t)Bc * Dc * Nc];
__device__ float g_h1[(size_t)Bc * 2 * Dc * Nc];

// ---------------------------------------------------------------------------
// Fast exp: FMA polynomial (avoids the MUFU throughput wall)
// ---------------------------------------------------------------------------
__device__ __forceinline__ float fexp(float x) {
    x = fmaxf(x, -87.0f);
    float t  = fmaf(x, 1.4426950408889634f, 12582912.0f);
    float fi = t - 12582912.0f;
    float f  = fmaf(x, 1.4426950408889634f, -fi);
    float p  = 1.3333558e-3f;
    p = fmaf(p, f, 9.6181291e-3f);
    p = fmaf(p, f, 5.5504109e-2f);
    p = fmaf(p, f, 2.4022651e-1f);
    p = fmaf(p, f, 6.9314718e-1f);
    p = fmaf(p, f, 1.0f);
    int e = (int)fi;
    return p * __int_as_float((e + 127) << 23);
}

// ---------------------------------------------------------------------------
// Tensor-core helpers: tf32 m16n8k8 mma + round-to-tf32 convert
// ---------------------------------------------------------------------------
__device__ __forceinline__ uint32_t f2tf(float x) {
    uint32_t r;
    asm("cvt.rna.tf32.f32 %0, %1;" : "=r"(r) : "f"(x));
    return r;
}
__device__ __forceinline__ float f2tf_f(float x) {
    return __uint_as_float(f2tf(x));
}
__device__ __forceinline__ void mma_tf32(float (&d)[4], const uint32_t (&a)[4],
                                         uint32_t b0, uint32_t b1) {
    asm volatile(
        "mma.sync.aligned.m16n8k8.row.col.f32.tf32.tf32.f32 "
        "{%0,%1,%2,%3}, {%4,%5,%6,%7}, {%8,%9}, {%0,%1,%2,%3};\n"
        : "+f"(d[0]), "+f"(d[1]), "+f"(d[2]), "+f"(d[3])
        : "r"(a[0]), "r"(a[1]), "r"(a[2]), "r"(a[3]), "r"(b0), "r"(b1));
}

// ---------------------------------------------------------------------------
// conv1x1 on tensor cores.
//   Y[o,n] = sum_i W[o,i] * X[i,n] + bias[o]   (optional relu; X = concat)
// Block: 256 threads / 8 warps; C-tile 64(o) x 128(n); warp tile 32x32
// (2 m-tiles x 4 n-tiles). A = W (row-major), B = X (natural [i][n]).
// Ws stride 20 and Xs stride 136 make all fragment LDS conflict-free.
// ---------------------------------------------------------------------------
#define WST 20
#define XST 136

__device__ __forceinline__ void conv_tile_mma(
    const float* __restrict__ W, const float* __restrict__ bias,
    const float* __restrict__ X1b, const float* __restrict__ X2b,
    float* __restrict__ Yb, int Din, int D1, int relu, int o0, int n0)
{
    __shared__ float Ws[64 * WST];
    __shared__ float Xs[16 * XST];

    const int tid  = threadIdx.x;
    const int warp = tid >> 5, lane = tid & 31;
    const int g  = lane >> 2, tc = lane & 3;
    const int wo = (warp & 1) * 32;     // warp o-offset within tile
    const int wn = (warp >> 1) * 32;    // warp n-offset within tile

    float d[2][4][4] = {};

    for (int k0 = 0; k0 < Din; k0 += 16) {
        // W tile: 64 rows x 16 cols
        {
            int c = tid & 15, r0 = tid >> 4;
            #pragma unroll
            for (int i = 0; i < 4; i++) {
                int rr = r0 + 16 * i;
                Ws[rr * WST + c] = f2tf_f(W[(size_t)(o0 + rr) * Din + k0 + c]);
            }
        }
        // X tile: 16 rows (i) x 128 cols (n), virtual concat
        {
            int n = tid & 127, rh = tid >> 7;
            #pragma unroll
            for (int i = 0; i < 8; i++) {
                int kk = rh + 2 * i;
                int c  = k0 + kk;
                const float* src = (c < D1) ? (X1b + (size_t)c * Nc)
                                            : (X2b + (size_t)(c - D1) * Nc);
                Xs[kk * XST + n] = f2tf_f(src[n0 + n]);
            }
        }
        __syncthreads();

        #pragma unroll
        for (int ks = 0; ks < 2; ks++) {
            uint32_t a[2][4];
            #pragma unroll
            for (int mt = 0; mt < 2; mt++) {
                const float* wr = &Ws[(wo + 16 * mt + g) * WST + 8 * ks + tc];
                a[mt][0] = __float_as_uint(wr[0]);
                a[mt][1] = __float_as_uint(wr[8 * WST]);
                a[mt][2] = __float_as_uint(wr[4]);
                a[mt][3] = __float_as_uint(wr[8 * WST + 4]);
            }
            #pragma unroll
            for (int jt = 0; jt < 4; jt++) {
                const float* xr = &Xs[(8 * ks + tc) * XST + wn + 8 * jt + g];
                uint32_t b0 = __float_as_uint(xr[0]);
                uint32_t b1 = __float_as_uint(xr[4 * XST]);
                mma_tf32(d[0][jt], a[0], b0, b1);
                mma_tf32(d[1][jt], a[1], b0, b1);
            }
        }
        __syncthreads();
    }

    // Epilogue: bias (+relu), float2 stores
    #pragma unroll
    for (int mt = 0; mt < 2; mt++) {
        int or0 = o0 + wo + 16 * mt + g;
        int or1 = or0 + 8;
        float bv0 = bias[or0], bv1 = bias[or1];
        #pragma unroll
        for (int jt = 0; jt < 4; jt++) {
            int nn = n0 + wn + 8 * jt + 2 * tc;
            float2 r0 = make_float2(d[mt][jt][0] + bv0, d[mt][jt][1] + bv0);
            float2 r1 = make_float2(d[mt][jt][2] + bv1, d[mt][jt][3] + bv1);
            if (relu) {
                r0.x = fmaxf(r0.x, 0.f); r0.y = fmaxf(r0.y, 0.f);
                r1.x = fmaxf(r1.x, 0.f); r1.y = fmaxf(r1.y, 0.f);
            }
            *(float2*)&Yb[(size_t)or0 * Nc + nn] = r0;
            *(float2*)&Yb[(size_t)or1 * Nc + nn] = r1;
        }
    }
}

// Generic conv kernel. grid: (N/128, Dout/64, B)
__global__ void __launch_bounds__(256)
k_conv_mma(const float* __restrict__ W, const float* __restrict__ bias,
           const float* __restrict__ X1, const float* __restrict__ X2,
           float* __restrict__ Y, int Dout, int D1, int D2, int relu)
{
    int b  = blockIdx.z;
    int n0 = blockIdx.x * 128;
    int o0 = blockIdx.y * 64;
    conv_tile_mma(W, bias,
                  X1 + (size_t)b * D1 * Nc,
                  X2 ? (X2 + (size_t)b * D2 * Nc) : nullptr,
                  Y + (size_t)b * Dout * Nc,
                  D1 + D2, D1, relu, o0, n0);
}

// Fused Q/K/V projections. grid: (N/128, 256/64, B*3)
__global__ void __launch_bounds__(256)
k_qkv_mma(const float* __restrict__ Wq, const float* __restrict__ bq,
          const float* __restrict__ Wk, const float* __restrict__ bk,
          const float* __restrict__ Wv, const float* __restrict__ bv,
          const float* __restrict__ x, const float* __restrict__ src,
          float* __restrict__ q, float* __restrict__ k, float* __restrict__ v)
{
    int z = blockIdx.z;
    int b = z / 3, which = z % 3;
    const float* W; const float* bias; const float* X; float* Y;
    if (which == 0)      { W = Wq; bias = bq; X = x;   Y = q; }
    else if (which == 1) { W = Wk; bias = bk; X = src; Y = k; }
    else                 { W = Wv; bias = bv; X = src; Y = v; }
    conv_tile_mma(W, bias, X + (size_t)b * Dc * Nc, nullptr,
                  Y + (size_t)b * Dc * Nc, Dc, Dc, 0,
                  blockIdx.y * 64, blockIdx.x * 128);
}

// ---------------------------------------------------------------------------
// Fused flash attention on tensor cores (unchanged from round 4).
// ---------------------------------------------------------------------------
#define KVS 72
#define FLASH_SMEM_FLOATS (3 * 64 * KVS + 128)
#define FLASH_SMEM_BYTES (FLASH_SMEM_FLOATS * 4)

__global__ void __launch_bounds__(128)
k_flash(const float* __restrict__ q, const float* __restrict__ k,
        const float* __restrict__ v, const float* __restrict__ edge,
        float* __restrict__ Msg)
{
    extern __shared__ float sm[];
    float* Ks = sm;
    float* Vs = sm + 64 * KVS;
    float* Ps = sm + 2 * 64 * KVS;
    float* cs = sm + 3 * 64 * KVS;
    float* zs = cs + 64;

    const int bh = blockIdx.y;
    const int b = bh >> 2, h = bh & 3;
    const int n0 = blockIdx.x * 64;

    const int tid  = threadIdx.x;
    const int warp = tid >> 5;
    const int lane = tid & 31;
    const int g  = lane >> 2;
    const int tc = lane & 3;
    const int nw = warp * 16;
    const int wd = warp * 16;

    const int lcol = tid & 63;
    const int lr   = tid >> 6;

    const float* qb = q + (size_t)b * Dc * Nc;
    const float* kb = k + (size_t)b * Dc * Nc;
    const float* vb = v + (size_t)b * Dc * Nc;

    uint32_t qa[8][4];
    #pragma unroll
    for (int kk = 0; kk < 8; kk++) {
        int ch0 = (8 * kk + tc) * 4 + h;
        int ch1 = (8 * kk + tc + 4) * 4 + h;
        qa[kk][0] = f2tf(qb[(size_t)ch0 * Nc + n0 + nw + g]);
        qa[kk][1] = f2tf(qb[(size_t)ch0 * Nc + n0 + nw + g + 8]);
        qa[kk][2] = f2tf(qb[(size_t)ch1 * Nc + n0 + nw + g]);
        qa[kk][3] = f2tf(qb[(size_t)ch1 * Nc + n0 + nw + g + 8]);
    }

    float o[8][4] = {};
    float mx0 = -1e30f, mx1 = -1e30f, Z0 = 0.f, Z1 = 0.f;

    const float* erow0 = edge + ((size_t)b * Nc + n0 + nw + g) * Nc + 2 * tc;
    const float* erow1 = erow0 + (size_t)8 * Nc;

    for (int m0 = 0; m0 < Nc; m0 += 64) {
        #pragma unroll 8
        for (int it = 0; it < 32; it++) {
            int dd = 2 * it + lr;
            size_t goff = (size_t)(dd * 4 + h) * Nc + m0 + lcol;
            Ks[dd * KVS + lcol] = f2tf_f(kb[goff]);
            Vs[dd * KVS + lcol] = f2tf_f(vb[goff]);
        }
        float2 e0[8], e1[8];
        #pragma unroll
        for (int j = 0; j < 8; j++) {
            e0[j] = *(const float2*)&erow0[m0 + 8 * j];
            e1[j] = *(const float2*)&erow1[m0 + 8 * j];
        }
        __syncthreads();

        float s[8][4] = {};
        #pragma unroll
        for (int kk = 0; kk < 8; kk++) {
            const float* kr0 = &Ks[(8 * kk + tc) * KVS + g];
            const float* kr1 = &Ks[(8 * kk + tc + 4) * KVS + g];
            #pragma unroll
            for (int j = 0; j < 8; j++) {
                uint32_t b0 = __float_as_uint(kr0[8 * j]);
                uint32_t b1 = __float_as_uint(kr1[8 * j]);
                mma_tf32(s[j], qa[kk], b0, b1);
            }
        }

        {
            float tm = -1e30f;
            #pragma unroll
            for (int j = 0; j < 8; j++)
                tm = fmaxf(tm, fmaxf(s[j][0], s[j][1]));
            tm *= 0.125f;
            tm = fmaxf(tm, __shfl_xor_sync(0xffffffffu, tm, 1));
            tm = fmaxf(tm, __shfl_xor_sync(0xffffffffu, tm, 2));
            float nm = fmaxf(mx0, tm);
            float c0 = fexp(mx0 - nm);
            mx0 = nm;
            float ts = 0.f;
            #pragma unroll
            for (int j = 0; j < 8; j++) {
                float p0 = fexp(fmaf(s[j][0], 0.125f, -nm));
                float p1 = fexp(fmaf(s[j][1], 0.125f, -nm));
                ts += p0 + p1;
                float2 pe = make_float2(f2tf_f(p0 * e0[j].x), f2tf_f(p1 * e0[j].y));
                *(float2*)&Ps[(nw + g) * KVS + 8 * j + 2 * tc] = pe;
            }
            ts += __shfl_xor_sync(0xffffffffu, ts, 1);
            ts += __shfl_xor_sync(0xffffffffu, ts, 2);
            Z0 = Z0 * c0 + ts;
            if (tc == 0) cs[nw + g] = c0;

            tm = -1e30f;
            #pragma unroll
            for (int j = 0; j < 8; j++)
                tm = fmaxf(tm, fmaxf(s[j][2], s[j][3]));
            tm *= 0.125f;
            tm = fmaxf(tm, __shfl_xor_sync(0xffffffffu, tm, 1));
            tm = fmaxf(tm, __shfl_xor_sync(0xffffffffu, tm, 2));
            nm = fmaxf(mx1, tm);
            float c1 = fexp(mx1 - nm);
            mx1 = nm;
            ts = 0.f;
            #pragma unroll
            for (int j = 0; j < 8; j++) {
                float p0 = fexp(fmaf(s[j][2], 0.125f, -nm));
                float p1 = fexp(fmaf(s[j][3], 0.125f, -nm));
                ts += p0 + p1;
                float2 pe = make_float2(f2tf_f(p0 * e1[j].x), f2tf_f(p1 * e1[j].y));
                *(float2*)&Ps[(nw + g + 8) * KVS + 8 * j + 2 * tc] = pe;
            }
            ts += __shfl_xor_sync(0xffffffffu, ts, 1);
            ts += __shfl_xor_sync(0xffffffffu, ts, 2);
            Z1 = Z1 * c1 + ts;
            if (tc == 0) cs[nw + g + 8] = c1;
        }
        __syncthreads();

        #pragma unroll
        for (int j = 0; j < 8; j++) {
            float cA = cs[8 * j + 2 * tc];
            float cB = cs[8 * j + 2 * tc + 1];
            o[j][0] *= cA; o[j][1] *= cB;
            o[j][2] *= cA; o[j][3] *= cB;
        }

        #pragma unroll
        for (int kk = 0; kk < 8; kk++) {
            uint32_t av[4];
            av[0] = __float_as_uint(Vs[(wd + g) * KVS + 8 * kk + tc]);
            av[1] = __float_as_uint(Vs[(wd + g + 8) * KVS + 8 * kk + tc]);
            av[2] = __float_as_uint(Vs[(wd + g) * KVS + 8 * kk + tc + 4]);
            av[3] = __float_as_uint(Vs[(wd + g + 8) * KVS + 8 * kk + tc + 4]);
            #pragma unroll
            for (int j = 0; j < 8; j++) {
                uint32_t b0 = __float_as_uint(Ps[(8 * j + g) * KVS + 8 * kk + tc]);
                uint32_t b1 = __float_as_uint(Ps[(8 * j + g) * KVS + 8 * kk + tc + 4]);
                mma_tf32(o[j], av, b0, b1);
            }
        }
        __syncthreads();
    }

    if (tc == 0) {
        zs[nw + g]     = 1.0f / Z0;
        zs[nw + g + 8] = 1.0f / Z1;
    }
    __syncthreads();

    #pragma unroll
    for (int j = 0; j < 8; j++) {
        float zi0 = zs[8 * j + 2 * tc];
        float zi1 = zs[8 * j + 2 * tc + 1];
        int ch0 = (wd + g) * 4 + h;
        int ch1 = (wd + g + 8) * 4 + h;
        float2 w0 = make_float2(o[j][0] * zi0, o[j][1] * zi1);
        float2 w1 = make_float2(o[j][2] * zi0, o[j][3] * zi1);
        *(float2*)&Msg[((size_t)b * Dc + ch0) * Nc + n0 + 8 * j + 2 * tc] = w0;
        *(float2*)&Msg[((size_t)b * Dc + ch1) * Nc + n0 + 8 * j + 2 * tc] = w1;
    }
}

// ---------------------------------------------------------------------------
// Launch
// ---------------------------------------------------------------------------
extern "C" void kernel_launch(void* const* d_in, const int* in_sizes, int n_in,
                              void* d_out, int out_size)
{
    const float* x    = (const float*)d_in[0];
    const float* src  = (const float*)d_in[1];
    const float* edge = (const float*)d_in[2];
    const float* Wq = (const float*)d_in[3];  const float* bq = (const float*)d_in[4];
    const float* Wk = (const float*)d_in[5];  const float* bk = (const float*)d_in[6];
    const float* Wv = (const float*)d_in[7];  const float* bv = (const float*)d_in[8];
    const float* Wm = (const float*)d_in[9];  const float* bm = (const float*)d_in[10];
    const float* W1 = (const float*)d_in[11]; const float* b1 = (const float*)d_in[12];
    const float* W2 = (const float*)d_in[13]; const float* b2 = (const float*)d_in[14];

    float *q, *k, *v, *msg, *message, *h1;
    cudaGetSymbolAddress((void**)&q,       g_q);
    cudaGetSymbolAddress((void**)&k,       g_k);
    cudaGetSymbolAddress((void**)&v,       g_v);
    cudaGetSymbolAddress((void**)&msg,     g_msg);
    cudaGetSymbolAddress((void**)&message, g_message);
    cudaGetSymbolAddress((void**)&h1,      g_h1);

    cudaFuncSetAttribute(k_flash, cudaFuncAttributeMaxDynamicSharedMemorySize,
                         FLASH_SMEM_BYTES);

    // fused Q/K/V projections (tensor cores)
    k_qkv_mma<<<dim3(Nc / 128, Dc / 64, Bc * 3), 256>>>(
        Wq, bq, Wk, bk, Wv, bv, x, src, q, k, v);

    // fused attention on tensor cores
    k_flash<<<dim3(Nc / 64, Bc * Hc), 128, FLASH_SMEM_BYTES>>>(q, k, v, edge, msg);

    // merge heads
    k_conv_mma<<<dim3(Nc / 128, Dc / 64, Bc), 256>>>(
        Wm, bm, msg, nullptr, message, Dc, Dc, 0, 0);

    // MLP on concat([x, message])
    k_conv_mma<<<dim3(Nc / 128, 2 * Dc / 64, Bc), 256>>>(
        W1, b1, x, message, h1, 2 * Dc, Dc, Dc, 1);
    k_conv_mma<<<dim3(Nc / 128, Dc / 64, Bc), 256>>>(
        W2, b2, h1, nullptr, (float*)d_out, Dc, 2 * Dc, 0, 0);
}

// round 6
// speedup vs baseline: 2.6370x; 1.3547x over previous
#include <cuda_runtime.h>
#include <cuda_bf16.h>
#include <cstdint>
#include <cstddef>

// Problem constants
#define Bc 4
#define Dc 256
#define Nc 2048
#define Hc 4
#define HD 64   // head dim

// ---------------------------------------------------------------------------
// Scratch (static device arrays; allocation APIs are forbidden)
// ---------------------------------------------------------------------------
__device__ float g_q[(size_t)Bc * Dc * Nc];
__device__ float g_k[(size_t)Bc * Dc * Nc];
__device__ float g_v[(size_t)Bc * Dc * Nc];
__device__ float g_msg[(size_t)Bc * Dc * Nc];
__device__ float g_message[(size_t)Bc * Dc * Nc];
__device__ float g_h1[(size_t)Bc * 2 * Dc * Nc];

// ---------------------------------------------------------------------------
// Fast exp: FMA polynomial
// ---------------------------------------------------------------------------
__device__ __forceinline__ float fexp(float x) {
    x = fmaxf(x, -87.0f);
    float t  = fmaf(x, 1.4426950408889634f, 12582912.0f);
    float fi = t - 12582912.0f;
    float f  = fmaf(x, 1.4426950408889634f, -fi);
    float p  = 1.3333558e-3f;
    p = fmaf(p, f, 9.6181291e-3f);
    p = fmaf(p, f, 5.5504109e-2f);
    p = fmaf(p, f, 2.4022651e-1f);
    p = fmaf(p, f, 6.9314718e-1f);
    p = fmaf(p, f, 1.0f);
    int e = (int)fi;
    return p * __int_as_float((e + 127) << 23);
}

// ---------------------------------------------------------------------------
// Tensor-core helpers
// ---------------------------------------------------------------------------
__device__ __forceinline__ uint32_t f2tf(float x) {
    uint32_t r;
    asm("cvt.rna.tf32.f32 %0, %1;" : "=r"(r) : "f"(x));
    return r;
}
__device__ __forceinline__ float f2tf_f(float x) {
    return __uint_as_float(f2tf(x));
}
__device__ __forceinline__ void mma_tf32(float (&d)[4], const uint32_t (&a)[4],
                                         uint32_t b0, uint32_t b1) {
    asm volatile(
        "mma.sync.aligned.m16n8k8.row.col.f32.tf32.tf32.f32 "
        "{%0,%1,%2,%3}, {%4,%5,%6,%7}, {%8,%9}, {%0,%1,%2,%3};\n"
        : "+f"(d[0]), "+f"(d[1]), "+f"(d[2]), "+f"(d[3])
        : "r"(a[0]), "r"(a[1]), "r"(a[2]), "r"(a[3]), "r"(b0), "r"(b1));
}
__device__ __forceinline__ void cpa16(uint32_t s, const float* g) {
    asm volatile("cp.async.cg.shared.global [%0], [%1], 16;" :: "r"(s), "l"(g) : "memory");
}
__device__ __forceinline__ void cpa_commit() {
    asm volatile("cp.async.commit_group;" ::: "memory");
}
__device__ __forceinline__ void cpa_wait2() {
    asm volatile("cp.async.wait_group 2;" ::: "memory");
}

// ---------------------------------------------------------------------------
// conv1x1 on tensor cores (round-5 core + optional tf32 rounding of outputs,
// needed so the flash cp.async path sees exactly-tf32 k/v — mma truncation
// of an already-rounded value is lossless).
// ---------------------------------------------------------------------------
#define WST 20
#define XST 136

__device__ __forceinline__ void conv_tile_mma(
    const float* __restrict__ W, const float* __restrict__ bias,
    const float* __restrict__ X1b, const float* __restrict__ X2b,
    float* __restrict__ Yb, int Din, int D1, int relu, int round_out,
    int o0, int n0)
{
    __shared__ float Ws[64 * WST];
    __shared__ float Xs[16 * XST];

    const int tid  = threadIdx.x;
    const int warp = tid >> 5, lane = tid & 31;
    const int g  = lane >> 2, tc = lane & 3;
    const int wo = (warp & 1) * 32;
    const int wn = (warp >> 1) * 32;

    float d[2][4][4] = {};

    for (int k0 = 0; k0 < Din; k0 += 16) {
        {
            int c = tid & 15, r0 = tid >> 4;
            #pragma unroll
            for (int i = 0; i < 4; i++) {
                int rr = r0 + 16 * i;
                Ws[rr * WST + c] = f2tf_f(W[(size_t)(o0 + rr) * Din + k0 + c]);
            }
        }
        {
            int n = tid & 127, rh = tid >> 7;
            #pragma unroll
            for (int i = 0; i < 8; i++) {
                int kk = rh + 2 * i;
                int c  = k0 + kk;
                const float* src = (c < D1) ? (X1b + (size_t)c * Nc)
                                            : (X2b + (size_t)(c - D1) * Nc);
                Xs[kk * XST + n] = f2tf_f(src[n0 + n]);
            }
        }
        __syncthreads();

        #pragma unroll
        for (int ks = 0; ks < 2; ks++) {
            uint32_t a[2][4];
            #pragma unroll
            for (int mt = 0; mt < 2; mt++) {
                const float* wr = &Ws[(wo + 16 * mt + g) * WST + 8 * ks + tc];
                a[mt][0] = __float_as_uint(wr[0]);
                a[mt][1] = __float_as_uint(wr[8 * WST]);
                a[mt][2] = __float_as_uint(wr[4]);
                a[mt][3] = __float_as_uint(wr[8 * WST + 4]);
            }
            #pragma unroll
            for (int jt = 0; jt < 4; jt++) {
                const float* xr = &Xs[(8 * ks + tc) * XST + wn + 8 * jt + g];
                uint32_t b0 = __float_as_uint(xr[0]);
                uint32_t b1 = __float_as_uint(xr[4 * XST]);
                mma_tf32(d[0][jt], a[0], b0, b1);
                mma_tf32(d[1][jt], a[1], b0, b1);
            }
        }
        __syncthreads();
    }

    #pragma unroll
    for (int mt = 0; mt < 2; mt++) {
        int or0 = o0 + wo + 16 * mt + g;
        int or1 = or0 + 8;
        float bv0 = bias[or0], bv1 = bias[or1];
        #pragma unroll
        for (int jt = 0; jt < 4; jt++) {
            int nn = n0 + wn + 8 * jt + 2 * tc;
            float2 r0 = make_float2(d[mt][jt][0] + bv0, d[mt][jt][1] + bv0);
            float2 r1 = make_float2(d[mt][jt][2] + bv1, d[mt][jt][3] + bv1);
            if (relu) {
                r0.x = fmaxf(r0.x, 0.f); r0.y = fmaxf(r0.y, 0.f);
                r1.x = fmaxf(r1.x, 0.f); r1.y = fmaxf(r1.y, 0.f);
            }
            if (round_out) {
                r0.x = f2tf_f(r0.x); r0.y = f2tf_f(r0.y);
                r1.x = f2tf_f(r1.x); r1.y = f2tf_f(r1.y);
            }
            *(float2*)&Yb[(size_t)or0 * Nc + nn] = r0;
            *(float2*)&Yb[(size_t)or1 * Nc + nn] = r1;
        }
    }
}

// Generic conv kernel. grid: (N/128, Dout/64, B)
__global__ void __launch_bounds__(256)
k_conv_mma(const float* __restrict__ W, const float* __restrict__ bias,
           const float* __restrict__ X1, const float* __restrict__ X2,
           float* __restrict__ Y, int Dout, int D1, int D2, int relu)
{
    int b  = blockIdx.z;
    conv_tile_mma(W, bias,
                  X1 + (size_t)b * D1 * Nc,
                  X2 ? (X2 + (size_t)b * D2 * Nc) : nullptr,
                  Y + (size_t)b * Dout * Nc,
                  D1 + D2, D1, relu, 0, blockIdx.y * 64, blockIdx.x * 128);
}

// Fused Q/K/V projections (outputs tf32-rounded). grid: (N/128, 256/64, B*3)
__global__ void __launch_bounds__(256)
k_qkv_mma(const float* __restrict__ Wq, const float* __restrict__ bq,
          const float* __restrict__ Wk, const float* __restrict__ bk,
          const float* __restrict__ Wv, const float* __restrict__ bv,
          const float* __restrict__ x, const float* __restrict__ src,
          float* __restrict__ q, float* __restrict__ k, float* __restrict__ v)
{
    int z = blockIdx.z;
    int b = z / 3, which = z % 3;
    const float* W; const float* bias; const float* X; float* Y;
    if (which == 0)      { W = Wq; bias = bq; X = x;   Y = q; }
    else if (which == 1) { W = Wk; bias = bk; X = src; Y = k; }
    else                 { W = Wv; bias = bv; X = src; Y = v; }
    conv_tile_mma(W, bias, X + (size_t)b * Dc * Nc, nullptr,
                  Y + (size_t)b * Dc * Nc, Dc, Dc, 0, 1,
                  blockIdx.y * 64, blockIdx.x * 128);
}

// ---------------------------------------------------------------------------
// Flash attention v2: no-max softmax + cp.async 3-stage rotating prefetch.
//   S = Q^T K (tensor), P = exp(S/8)*edge (Z excludes edge), O^T = V P^T.
// Buffers: Ks/Vs/Es/Ps, each 64 x KVS. Commit order K,E,V -> wait_group 2
// at every consume point. Prefetch slots: K after S-GEMM, E after softmax,
// V after PV (each into its own then-dead buffer).
// grid: (N/64, B*H), 128 threads
// ---------------------------------------------------------------------------
#define KVS 72
#define FLASH_SMEM_FLOATS (4 * 64 * KVS + 64)
#define FLASH_SMEM_BYTES (FLASH_SMEM_FLOATS * 4)
#define NTILES (Nc / 64)

__global__ void __launch_bounds__(128)
k_flash(const float* __restrict__ q, const float* __restrict__ k,
        const float* __restrict__ v, const float* __restrict__ edge,
        float* __restrict__ Msg)
{
    extern __shared__ float sm[];
    float* Ks = sm;
    float* Vs = sm + 64 * KVS;
    float* Es = sm + 2 * 64 * KVS;
    float* Ps = sm + 3 * 64 * KVS;
    float* zs = sm + 4 * 64 * KVS;

    const int bh = blockIdx.y;
    const int b = bh >> 2, h = bh & 3;
    const int n0 = blockIdx.x * 64;

    const int tid  = threadIdx.x;
    const int warp = tid >> 5;
    const int lane = tid & 31;
    const int g  = lane >> 2;
    const int tc = lane & 3;
    const int nw = warp * 16;   // n-strip (S/softmax)
    const int wd = warp * 16;   // dd-strip (PV)

    const uint32_t ks_u = (uint32_t)__cvta_generic_to_shared(Ks);
    const uint32_t vs_u = (uint32_t)__cvta_generic_to_shared(Vs);
    const uint32_t es_u = (uint32_t)__cvta_generic_to_shared(Es);

    const float* qb = q + (size_t)b * Dc * Nc;
    const float* kb = k + (size_t)b * Dc * Nc;
    const float* vb = v + (size_t)b * Dc * Nc;
    const float* eb = edge + (size_t)b * Nc * Nc + n0 * (size_t)Nc;

    // copy mapping: 8 chunks/thread; row = (tid>>4)+8i, col = (tid&15)*4
    const int crow = tid >> 4;
    const int ccol = (tid & 15) * 4;

    // --- Q a-fragments, resident ---
    uint32_t qa[8][4];
    #pragma unroll
    for (int kk = 0; kk < 8; kk++) {
        int ch0 = (8 * kk + tc) * 4 + h;
        int ch1 = (8 * kk + tc + 4) * 4 + h;
        qa[kk][0] = f2tf(qb[(size_t)ch0 * Nc + n0 + nw + g]);
        qa[kk][1] = f2tf(qb[(size_t)ch0 * Nc + n0 + nw + g + 8]);
        qa[kk][2] = f2tf(qb[(size_t)ch1 * Nc + n0 + nw + g]);
        qa[kk][3] = f2tf(qb[(size_t)ch1 * Nc + n0 + nw + g + 8]);
    }

    auto issueK = [&](int m0) {
        #pragma unroll
        for (int i = 0; i < 8; i++) {
            int dd = crow + 8 * i;
            cpa16(ks_u + (uint32_t)(dd * KVS + ccol) * 4,
                  kb + (size_t)(dd * 4 + h) * Nc + m0 + ccol);
        }
        cpa_commit();
    };
    auto issueE = [&](int m0) {
        #pragma unroll
        for (int i = 0; i < 8; i++) {
            int nn = crow + 8 * i;
            cpa16(es_u + (uint32_t)(nn * KVS + ccol) * 4,
                  eb + (size_t)nn * Nc + m0 + ccol);
        }
        cpa_commit();
    };
    auto issueV = [&](int m0) {
        #pragma unroll
        for (int i = 0; i < 8; i++) {
            int dd = crow + 8 * i;
            cpa16(vs_u + (uint32_t)(dd * KVS + ccol) * 4,
                  vb + (size_t)(dd * 4 + h) * Nc + m0 + ccol);
        }
        cpa_commit();
    };

    // prologue: 3 groups in flight (commit order K, E, V)
    issueK(0);
    issueE(0);
    issueV(0);

    float o[8][4] = {};
    float Z0 = 0.f, Z1 = 0.f;

    for (int t = 0; t < NTILES; t++) {
        const int mn = (t + 1 < NTILES) ? (t + 1) * 64 : 0;  // wrap: harmless

        cpa_wait2(); __syncthreads();         // K(t) visible
        // --- S = Q^T K ---
        float s[8][4] = {};
        #pragma unroll
        for (int kk = 0; kk < 8; kk++) {
            const float* kr0 = &Ks[(8 * kk + tc) * KVS + g];
            const float* kr1 = &Ks[(8 * kk + tc + 4) * KVS + g];
            #pragma unroll
            for (int j = 0; j < 8; j++) {
                uint32_t b0 = __float_as_uint(kr0[8 * j]);
                uint32_t b1 = __float_as_uint(kr1[8 * j]);
                mma_tf32(s[j], qa[kk], b0, b1);
            }
        }
        __syncthreads();                      // Ks dead
        issueK(mn);

        cpa_wait2(); __syncthreads();         // E(t) visible
        // --- softmax without max-subtraction; P = exp(s/8)*e ---
        #pragma unroll
        for (int j = 0; j < 8; j++) {
            float2 e0 = *(const float2*)&Es[(nw + g) * KVS + 8 * j + 2 * tc];
            float2 e1 = *(const float2*)&Es[(nw + g + 8) * KVS + 8 * j + 2 * tc];
            float p00 = fexp(s[j][0] * 0.125f);
            float p01 = fexp(s[j][1] * 0.125f);
            float p10 = fexp(s[j][2] * 0.125f);
            float p11 = fexp(s[j][3] * 0.125f);
            Z0 += p00 + p01;
            Z1 += p10 + p11;
            *(float2*)&Ps[(nw + g) * KVS + 8 * j + 2 * tc] =
                make_float2(f2tf_f(p00 * e0.x), f2tf_f(p01 * e0.y));
            *(float2*)&Ps[(nw + g + 8) * KVS + 8 * j + 2 * tc] =
                make_float2(f2tf_f(p10 * e1.x), f2tf_f(p11 * e1.y));
        }
        __syncthreads();                      // Es dead; Ps complete
        issueE(mn);

        cpa_wait2(); __syncthreads();         // V(t) visible
        // --- O^T += V * P^T ---
        #pragma unroll
        for (int kk = 0; kk < 8; kk++) {
            uint32_t av[4];
            av[0] = __float_as_uint(Vs[(wd + g) * KVS + 8 * kk + tc]);
            av[1] = __float_as_uint(Vs[(wd + g + 8) * KVS + 8 * kk + tc]);
            av[2] = __float_as_uint(Vs[(wd + g) * KVS + 8 * kk + tc + 4]);
            av[3] = __float_as_uint(Vs[(wd + g + 8) * KVS + 8 * kk + tc + 4]);
            #pragma unroll
            for (int j = 0; j < 8; j++) {
                uint32_t b0 = __float_as_uint(Ps[(8 * j + g) * KVS + 8 * kk + tc]);
                uint32_t b1 = __float_as_uint(Ps[(8 * j + g) * KVS + 8 * kk + tc + 4]);
                mma_tf32(o[j], av, b0, b1);
            }
        }
        __syncthreads();                      // Vs, Ps dead
        issueV(mn);
    }

    // --- epilogue: quad-reduce Z per row, publish 1/Z, write O^T/Z ---
    Z0 += __shfl_xor_sync(0xffffffffu, Z0, 1);
    Z0 += __shfl_xor_sync(0xffffffffu, Z0, 2);
    Z1 += __shfl_xor_sync(0xffffffffu, Z1, 1);
    Z1 += __shfl_xor_sync(0xffffffffu, Z1, 2);
    if (tc == 0) {
        zs[nw + g]     = 1.0f / Z0;
        zs[nw + g + 8] = 1.0f / Z1;
    }
    __syncthreads();

    #pragma unroll
    for (int j = 0; j < 8; j++) {
        float zi0 = zs[8 * j + 2 * tc];
        float zi1 = zs[8 * j + 2 * tc + 1];
        int ch0 = (wd + g) * 4 + h;
        int ch1 = (wd + g + 8) * 4 + h;
        float2 w0 = make_float2(o[j][0] * zi0, o[j][1] * zi1);
        float2 w1 = make_float2(o[j][2] * zi0, o[j][3] * zi1);
        *(float2*)&Msg[((size_t)b * Dc + ch0) * Nc + n0 + 8 * j + 2 * tc] = w0;
        *(float2*)&Msg[((size_t)b * Dc + ch1) * Nc + n0 + 8 * j + 2 * tc] = w1;
    }
}

// ---------------------------------------------------------------------------
// Launch
// ---------------------------------------------------------------------------
extern "C" void kernel_launch(void* const* d_in, const int* in_sizes, int n_in,
                              void* d_out, int out_size)
{
    const float* x    = (const float*)d_in[0];
    const float* src  = (const float*)d_in[1];
    const float* edge = (const float*)d_in[2];
    const float* Wq = (const float*)d_in[3];  const float* bq = (const float*)d_in[4];
    const float* Wk = (const float*)d_in[5];  const float* bk = (const float*)d_in[6];
    const float* Wv = (const float*)d_in[7];  const float* bv = (const float*)d_in[8];
    const float* Wm = (const float*)d_in[9];  const float* bm = (const float*)d_in[10];
    const float* W1 = (const float*)d_in[11]; const float* b1 = (const float*)d_in[12];
    const float* W2 = (const float*)d_in[13]; const float* b2 = (const float*)d_in[14];

    float *q, *k, *v, *msg, *message, *h1;
    cudaGetSymbolAddress((void**)&q,       g_q);
    cudaGetSymbolAddress((void**)&k,       g_k);
    cudaGetSymbolAddress((void**)&v,       g_v);
    cudaGetSymbolAddress((void**)&msg,     g_msg);
    cudaGetSymbolAddress((void**)&message, g_message);
    cudaGetSymbolAddress((void**)&h1,      g_h1);

    cudaFuncSetAttribute(k_flash, cudaFuncAttributeMaxDynamicSharedMemorySize,
                         FLASH_SMEM_BYTES);

    // fused Q/K/V projections (tensor cores, tf32-rounded outputs)
    k_qkv_mma<<<dim3(Nc / 128, Dc / 64, Bc * 3), 256>>>(
        Wq, bq, Wk, bk, Wv, bv, x, src, q, k, v);

    // fused attention (tensor cores + cp.async pipeline)
    k_flash<<<dim3(Nc / 64, Bc * Hc), 128, FLASH_SMEM_BYTES>>>(q, k, v, edge, msg);

    // merge heads
    k_conv_mma<<<dim3(Nc / 128, Dc / 64, Bc), 256>>>(
        Wm, bm, msg, nullptr, message, Dc, Dc, 0, 0);

    // MLP on concat([x, message])
    k_conv_mma<<<dim3(Nc / 128, 2 * Dc / 64, Bc), 256>>>(
        W1, b1, x, message, h1, 2 * Dc, Dc, Dc, 1);
    k_conv_mma<<<dim3(Nc / 128, Dc / 64, Bc), 256>>>(
        W2, b2, h1, nullptr, (float*)d_out, Dc, 2 * Dc, 0, 0);
}

// round 8
// speedup vs baseline: 3.3447x; 1.2684x over previous
#include <cuda_runtime.h>
#include <cuda_bf16.h>
#include <cstdint>
#include <cstddef>

// Problem constants
#define Bc 4
#define Dc 256
#define Nc 2048
#define Hc 4
#define HD 64   // head dim

// ---------------------------------------------------------------------------
// Scratch (static device arrays; allocation APIs are forbidden)
// ---------------------------------------------------------------------------
__device__ float g_q[(size_t)Bc * Dc * Nc];
__device__ float g_k[(size_t)Bc * Dc * Nc];
__device__ float g_v[(size_t)Bc * Dc * Nc];
__device__ float g_msg[(size_t)Bc * Dc * Nc];
__device__ float g_message[(size_t)Bc * Dc * Nc];
__device__ float g_h1[(size_t)Bc * 2 * Dc * Nc];
// tf32-rounded copies (so conv cp.async is conversion-free AND lossless)
__device__ float g_rx[(size_t)Bc * Dc * Nc];
__device__ float g_rs[(size_t)Bc * Dc * Nc];
__device__ float g_rWq[Dc * Dc];
__device__ float g_rWk[Dc * Dc];
__device__ float g_rWv[Dc * Dc];
__device__ float g_rWm[Dc * Dc];
__device__ float g_rW1[2 * Dc * 2 * Dc];
__device__ float g_rW2[Dc * 2 * Dc];

// ---------------------------------------------------------------------------
// Fast exp: FMA polynomial
// ---------------------------------------------------------------------------
__device__ __forceinline__ float fexp(float x) {
    x = fmaxf(x, -87.0f);
    float t  = fmaf(x, 1.4426950408889634f, 12582912.0f);
    float fi = t - 12582912.0f;
    float f  = fmaf(x, 1.4426950408889634f, -fi);
    float p  = 1.3333558e-3f;
    p = fmaf(p, f, 9.6181291e-3f);
    p = fmaf(p, f, 5.5504109e-2f);
    p = fmaf(p, f, 2.4022651e-1f);
    p = fmaf(p, f, 6.9314718e-1f);
    p = fmaf(p, f, 1.0f);
    int e = (int)fi;
    return p * __int_as_float((e + 127) << 23);
}

// ---------------------------------------------------------------------------
// Tensor-core / async-copy helpers
// ---------------------------------------------------------------------------
__device__ __forceinline__ uint32_t f2tf(float x) {
    uint32_t r;
    asm("cvt.rna.tf32.f32 %0, %1;" : "=r"(r) : "f"(x));
    return r;
}
__device__ __forceinline__ float f2tf_f(float x) {
    return __uint_as_float(f2tf(x));
}
__device__ __forceinline__ void mma_tf32(float (&d)[4], const uint32_t (&a)[4],
                                         uint32_t b0, uint32_t b1) {
    asm volatile(
        "mma.sync.aligned.m16n8k8.row.col.f32.tf32.tf32.f32 "
        "{%0,%1,%2,%3}, {%4,%5,%6,%7}, {%8,%9}, {%0,%1,%2,%3};\n"
        : "+f"(d[0]), "+f"(d[1]), "+f"(d[2]), "+f"(d[3])
        : "r"(a[0]), "r"(a[1]), "r"(a[2]), "r"(a[3]), "r"(b0), "r"(b1));
}
__device__ __forceinline__ void cpa16(uint32_t s, const float* g) {
    asm volatile("cp.async.cg.shared.global [%0], [%1], 16;" :: "r"(s), "l"(g) : "memory");
}
__device__ __forceinline__ void cpa_commit() {
    asm volatile("cp.async.commit_group;" ::: "memory");
}
__device__ __forceinline__ void cpa_wait2() {
    asm volatile("cp.async.wait_group 2;" ::: "memory");
}

// ---------------------------------------------------------------------------
// tf32 pre-round pass (elementwise, float4)
// ---------------------------------------------------------------------------
__global__ void k_round(const float4* __restrict__ s, float4* __restrict__ d, int n4)
{
    int i = blockIdx.x * blockDim.x + threadIdx.x;
    if (i < n4) {
        float4 t = s[i];
        t.x = f2tf_f(t.x); t.y = f2tf_f(t.y);
        t.z = f2tf_f(t.z); t.w = f2tf_f(t.w);
        d[i] = t;
    }
}

// ---------------------------------------------------------------------------
// conv1x1 on tensor cores, v2: 4-stage cp.async pipeline, ONE sync per K-step.
// All inputs (W and X) must already be exactly-tf32 (prepass / producer
// epilogues), so cp.async needs no conversion and mma truncation is lossless.
// C-tile 64(o) x 128(n), 8 warps, warp tile 32x32, K-step 16.
// Stage = W tile [64][20] + X tile [16][136]; 4 stages, wait_group 2.
// ---------------------------------------------------------------------------
#define CWST 20
#define CXST 136
#define CBUF (64 * CWST + 16 * CXST)         // 3456 floats per stage
#define CONV_SMEM_BYTES (4 * CBUF * 4)       // 55296 B

__device__ __forceinline__ void conv_tile_mma(
    const float* __restrict__ W, const float* __restrict__ bias,
    const float* __restrict__ X1b, const float* __restrict__ X2b,
    float* __restrict__ Yb, int Din, int D1, int relu, int round_out,
    int o0, int n0, float* smbase)
{
    const int tid  = threadIdx.x;
    const int warp = tid >> 5, lane = tid & 31;
    const int g  = lane >> 2, tc = lane & 3;
    const int wo = (warp & 1) * 32;
    const int wn = (warp >> 1) * 32;
    const int niter = Din >> 4;

    float* stg[4] = {smbase, smbase + CBUF, smbase + 2 * CBUF, smbase + 3 * CBUF};

    // cp.async mapping: W 256 chunks (1/thread), X 512 chunks (2/thread)
    const int wrow = tid >> 2, wkc = (tid & 3) * 4;

    auto issue = [&](int k0, float* buf) {
        uint32_t bu = (uint32_t)__cvta_generic_to_shared(buf);
        cpa16(bu + (uint32_t)(wrow * CWST + wkc) * 4,
              W + (size_t)(o0 + wrow) * Din + k0 + wkc);
        #pragma unroll
        for (int i = 0; i < 2; i++) {
            int c   = tid + 256 * i;
            int row = c >> 5, col = (c & 31) * 4;
            int ch  = k0 + row;
            const float* s = (ch < D1) ? (X1b + (size_t)ch * Nc)
                                       : (X2b + (size_t)(ch - D1) * Nc);
            cpa16(bu + (uint32_t)(64 * CWST + row * CXST + col) * 4, s + n0 + col);
        }
        cpa_commit();
    };

    issue(0, stg[0]);
    issue(16, stg[1]);
    issue(32, stg[2]);

    float d[2][4][4] = {};

    for (int it = 0; it < niter; it++) {
        cpa_wait2();
        __syncthreads();
        const float* Wst = stg[it & 3];
        const float* Xst = Wst + 64 * CWST;

        #pragma unroll
        for (int ks = 0; ks < 2; ks++) {
            uint32_t a[2][4];
            #pragma unroll
            for (int mt = 0; mt < 2; mt++) {
                const float* wr = &Wst[(wo + 16 * mt + g) * CWST + 8 * ks + tc];
                a[mt][0] = __float_as_uint(wr[0]);
                a[mt][1] = __float_as_uint(wr[8 * CWST]);
                a[mt][2] = __float_as_uint(wr[4]);
                a[mt][3] = __float_as_uint(wr[8 * CWST + 4]);
            }
            #pragma unroll
            for (int jt = 0; jt < 4; jt++) {
                const float* xr = &Xst[(8 * ks + tc) * CXST + wn + 8 * jt + g];
                uint32_t b0 = __float_as_uint(xr[0]);
                uint32_t b1 = __float_as_uint(xr[4 * CXST]);
                mma_tf32(d[0][jt], a[0], b0, b1);
                mma_tf32(d[1][jt], a[1], b0, b1);
            }
        }

        int nit = it + 3;
        if (nit < niter) issue(nit * 16, stg[nit & 3]);
        else             cpa_commit();       // keep group count constant
    }

    #pragma unroll
    for (int mt = 0; mt < 2; mt++) {
        int or0 = o0 + wo + 16 * mt + g;
        int or1 = or0 + 8;
        float bv0 = bias[or0], bv1 = bias[or1];
        #pragma unroll
        for (int jt = 0; jt < 4; jt++) {
            int nn = n0 + wn + 8 * jt + 2 * tc;
            float2 r0 = make_float2(d[mt][jt][0] + bv0, d[mt][jt][1] + bv0);
            float2 r1 = make_float2(d[mt][jt][2] + bv1, d[mt][jt][3] + bv1);
            if (relu) {
                r0.x = fmaxf(r0.x, 0.f); r0.y = fmaxf(r0.y, 0.f);
                r1.x = fmaxf(r1.x, 0.f); r1.y = fmaxf(r1.y, 0.f);
            }
            if (round_out) {
                r0.x = f2tf_f(r0.x); r0.y = f2tf_f(r0.y);
                r1.x = f2tf_f(r1.x); r1.y = f2tf_f(r1.y);
            }
            *(float2*)&Yb[(size_t)or0 * Nc + nn] = r0;
            *(float2*)&Yb[(size_t)or1 * Nc + nn] = r1;
        }
    }
}

// Generic conv kernel. grid: (N/128, Dout/64, B)
__global__ void __launch_bounds__(256)
k_conv_mma(const float* __restrict__ W, const float* __restrict__ bias,
           const float* __restrict__ X1, const float* __restrict__ X2,
           float* __restrict__ Y, int Dout, int D1, int D2, int relu,
           int round_out)
{
    extern __shared__ float smc[];
    int b = blockIdx.z;
    conv_tile_mma(W, bias,
                  X1 + (size_t)b * D1 * Nc,
                  X2 ? (X2 + (size_t)b * D2 * Nc) : nullptr,
                  Y + (size_t)b * Dout * Nc,
                  D1 + D2, D1, relu, round_out,
                  blockIdx.y * 64, blockIdx.x * 128, smc);
}

// Fused Q/K/V projections (tf32-rounded outputs). grid: (N/128, 256/64, B*3)
__global__ void __launch_bounds__(256)
k_qkv_mma(const float* __restrict__ Wq, const float* __restrict__ bq,
          const float* __restrict__ Wk, const float* __restrict__ bk,
          const float* __restrict__ Wv, const float* __restrict__ bv,
          const float* __restrict__ x, const float* __restrict__ src,
          float* __restrict__ q, float* __restrict__ k, float* __restrict__ v)
{
    extern __shared__ float smc[];
    int z = blockIdx.z;
    int b = z / 3, which = z % 3;
    const float* W; const float* bias; const float* X; float* Y;
    if (which == 0)      { W = Wq; bias = bq; X = x;   Y = q; }
    else if (which == 1) { W = Wk; bias = bk; X = src; Y = k; }
    else                 { W = Wv; bias = bv; X = src; Y = v; }
    conv_tile_mma(W, bias, X + (size_t)b * Dc * Nc, nullptr,
                  Y + (size_t)b * Dc * Nc, Dc, Dc, 0, 1,
                  blockIdx.y * 64, blockIdx.x * 128, smc);
}

// ---------------------------------------------------------------------------
// Flash attention (round-6 design; msg tf32-rounded at epilogue so the
// Wm conv can cp.async it losslessly).
// ---------------------------------------------------------------------------
#define KVS 72
#define FLASH_SMEM_FLOATS (4 * 64 * KVS + 64)
#define FLASH_SMEM_BYTES (FLASH_SMEM_FLOATS * 4)
#define NTILES (Nc / 64)

__global__ void __launch_bounds__(128)
k_flash(const float* __restrict__ q, const float* __restrict__ k,
        const float* __restrict__ v, const float* __restrict__ edge,
        float* __restrict__ Msg)
{
    extern __shared__ float sm[];
    float* Ks = sm;
    float* Vs = sm + 64 * KVS;
    float* Es = sm + 2 * 64 * KVS;
    float* Ps = sm + 3 * 64 * KVS;
    float* zs = sm + 4 * 64 * KVS;

    const int bh = blockIdx.y;
    const int b = bh >> 2, h = bh & 3;
    const int n0 = blockIdx.x * 64;

    const int tid  = threadIdx.x;
    const int warp = tid >> 5;
    const int lane = tid & 31;
    const int g  = lane >> 2;
    const int tc = lane & 3;
    const int nw = warp * 16;
    const int wd = warp * 16;

    const uint32_t ks_u = (uint32_t)__cvta_generic_to_shared(Ks);
    const uint32_t vs_u = (uint32_t)__cvta_generic_to_shared(Vs);
    const uint32_t es_u = (uint32_t)__cvta_generic_to_shared(Es);

    const float* qb = q + (size_t)b * Dc * Nc;
    const float* kb = k + (size_t)b * Dc * Nc;
    const float* vb = v + (size_t)b * Dc * Nc;
    const float* eb = edge + (size_t)b * Nc * Nc + n0 * (size_t)Nc;

    const int crow = tid >> 4;
    const int ccol = (tid & 15) * 4;

    uint32_t qa[8][4];
    #pragma unroll
    for (int kk = 0; kk < 8; kk++) {
        int ch0 = (8 * kk + tc) * 4 + h;
        int ch1 = (8 * kk + tc + 4) * 4 + h;
        qa[kk][0] = f2tf(qb[(size_t)ch0 * Nc + n0 + nw + g]);
        qa[kk][1] = f2tf(qb[(size_t)ch0 * Nc + n0 + nw + g + 8]);
        qa[kk][2] = f2tf(qb[(size_t)ch1 * Nc + n0 + nw + g]);
        qa[kk][3] = f2tf(qb[(size_t)ch1 * Nc + n0 + nw + g + 8]);
    }

    auto issueK = [&](int m0) {
        #pragma unroll
        for (int i = 0; i < 8; i++) {
            int dd = crow + 8 * i;
            cpa16(ks_u + (uint32_t)(dd * KVS + ccol) * 4,
                  kb + (size_t)(dd * 4 + h) * Nc + m0 + ccol);
        }
        cpa_commit();
    };
    auto issueE = [&](int m0) {
        #pragma unroll
        for (int i = 0; i < 8; i++) {
            int nn = crow + 8 * i;
            cpa16(es_u + (uint32_t)(nn * KVS + ccol) * 4,
                  eb + (size_t)nn * Nc + m0 + ccol);
        }
        cpa_commit();
    };
    auto issueV = [&](int m0) {
        #pragma unroll
        for (int i = 0; i < 8; i++) {
            int dd = crow + 8 * i;
            cpa16(vs_u + (uint32_t)(dd * KVS + ccol) * 4,
                  vb + (size_t)(dd * 4 + h) * Nc + m0 + ccol);
        }
        cpa_commit();
    };

    issueK(0);
    issueE(0);
    issueV(0);

    float o[8][4] = {};
    float Z0 = 0.f, Z1 = 0.f;

    for (int t = 0; t < NTILES; t++) {
        const int mn = (t + 1 < NTILES) ? (t + 1) * 64 : 0;

        cpa_wait2(); __syncthreads();
        float s[8][4] = {};
        #pragma unroll
        for (int kk = 0; kk < 8; kk++) {
            const float* kr0 = &Ks[(8 * kk + tc) * KVS + g];
            const float* kr1 = &Ks[(8 * kk + tc + 4) * KVS + g];
            #pragma unroll
            for (int j = 0; j < 8; j++) {
                uint32_t b0 = __float_as_uint(kr0[8 * j]);
                uint32_t b1 = __float_as_uint(kr1[8 * j]);
                mma_tf32(s[j], qa[kk], b0, b1);
            }
        }
        __syncthreads();
        issueK(mn);

        cpa_wait2(); __syncthreads();
        #pragma unroll
        for (int j = 0; j < 8; j++) {
            float2 e0 = *(const float2*)&Es[(nw + g) * KVS + 8 * j + 2 * tc];
            float2 e1 = *(const float2*)&Es[(nw + g + 8) * KVS + 8 * j + 2 * tc];
            float p00 = fexp(s[j][0] * 0.125f);
            float p01 = fexp(s[j][1] * 0.125f);
            float p10 = fexp(s[j][2] * 0.125f);
            float p11 = fexp(s[j][3] * 0.125f);
            Z0 += p00 + p01;
            Z1 += p10 + p11;
            *(float2*)&Ps[(nw + g) * KVS + 8 * j + 2 * tc] =
                make_float2(f2tf_f(p00 * e0.x), f2tf_f(p01 * e0.y));
            *(float2*)&Ps[(nw + g + 8) * KVS + 8 * j + 2 * tc] =
                make_float2(f2tf_f(p10 * e1.x), f2tf_f(p11 * e1.y));
        }
        __syncthreads();
        issueE(mn);

        cpa_wait2(); __syncthreads();
        #pragma unroll
        for (int kk = 0; kk < 8; kk++) {
            uint32_t av[4];
            av[0] = __float_as_uint(Vs[(wd + g) * KVS + 8 * kk + tc]);
            av[1] = __float_as_uint(Vs[(wd + g + 8) * KVS + 8 * kk + tc]);
            av[2] = __float_as_uint(Vs[(wd + g) * KVS + 8 * kk + tc + 4]);
            av[3] = __float_as_uint(Vs[(wd + g + 8) * KVS + 8 * kk + tc + 4]);
            #pragma unroll
            for (int j = 0; j < 8; j++) {
                uint32_t b0 = __float_as_uint(Ps[(8 * j + g) * KVS + 8 * kk + tc]);
                uint32_t b1 = __float_as_uint(Ps[(8 * j + g) * KVS + 8 * kk + tc + 4]);
                mma_tf32(o[j], av, b0, b1);
            }
        }
        __syncthreads();
        issueV(mn);
    }

    Z0 += __shfl_xor_sync(0xffffffffu, Z0, 1);
    Z0 += __shfl_xor_sync(0xffffffffu, Z0, 2);
    Z1 += __shfl_xor_sync(0xffffffffu, Z1, 1);
    Z1 += __shfl_xor_sync(0xffffffffu, Z1, 2);
    if (tc == 0) {
        zs[nw + g]     = 1.0f / Z0;
        zs[nw + g + 8] = 1.0f / Z1;
    }
    __syncthreads();

    #pragma unroll
    for (int j = 0; j < 8; j++) {
        float zi0 = zs[8 * j + 2 * tc];
        float zi1 = zs[8 * j + 2 * tc + 1];
        int ch0 = (wd + g) * 4 + h;
        int ch1 = (wd + g + 8) * 4 + h;
        float2 w0 = make_float2(f2tf_f(o[j][0] * zi0), f2tf_f(o[j][1] * zi1));
        float2 w1 = make_float2(f2tf_f(o[j][2] * zi0), f2tf_f(o[j][3] * zi1));
        *(float2*)&Msg[((size_t)b * Dc + ch0) * Nc + n0 + 8 * j + 2 * tc] = w0;
        *(float2*)&Msg[((size_t)b * Dc + ch1) * Nc + n0 + 8 * j + 2 * tc] = w1;
    }
}

// ---------------------------------------------------------------------------
// Launch
// ---------------------------------------------------------------------------
extern "C" void kernel_launch(void* const* d_in, const int* in_sizes, int n_in,
                              void* d_out, int out_size)
{
    const float* x    = (const float*)d_in[0];
    const float* src  = (const float*)d_in[1];
    const float* edge = (const float*)d_in[2];
    const float* Wq = (const float*)d_in[3];  const float* bq = (const float*)d_in[4];
    const float* Wk = (const float*)d_in[5];  const float* bk = (const float*)d_in[6];
    const float* Wv = (const float*)d_in[7];  const float* bv = (const float*)d_in[8];
    const float* Wm = (const float*)d_in[9];  const float* bm = (const float*)d_in[10];
    const float* W1 = (const float*)d_in[11]; const float* b1 = (const float*)d_in[12];
    const float* W2 = (const float*)d_in[13]; const float* b2 = (const float*)d_in[14];

    float *q, *k, *v, *msg, *message, *h1;
    float *rx, *rs, *rWq, *rWk, *rWv, *rWm, *rW1, *rW2;
    cudaGetSymbolAddress((void**)&q,       g_q);
    cudaGetSymbolAddress((void**)&k,       g_k);
    cudaGetSymbolAddress((void**)&v,       g_v);
    cudaGetSymbolAddress((void**)&msg,     g_msg);
    cudaGetSymbolAddress((void**)&message, g_message);
    cudaGetSymbolAddress((void**)&h1,      g_h1);
    cudaGetSymbolAddress((void**)&rx,      g_rx);
    cudaGetSymbolAddress((void**)&rs,      g_rs);
    cudaGetSymbolAddress((void**)&rWq,     g_rWq);
    cudaGetSymbolAddress((void**)&rWk,     g_rWk);
    cudaGetSymbolAddress((void**)&rWv,     g_rWv);
    cudaGetSymbolAddress((void**)&rWm,     g_rWm);
    cudaGetSymbolAddress((void**)&rW1,     g_rW1);
    cudaGetSymbolAddress((void**)&rW2,     g_rW2);

    cudaFuncSetAttribute(k_flash, cudaFuncAttributeMaxDynamicSharedMemorySize,
                         FLASH_SMEM_BYTES);
    cudaFuncSetAttribute(k_conv_mma, cudaFuncAttributeMaxDynamicSharedMemorySize,
                         CONV_SMEM_BYTES);
    cudaFuncSetAttribute(k_qkv_mma, cudaFuncAttributeMaxDynamicSharedMemorySize,
                         CONV_SMEM_BYTES);

    // tf32 pre-round of raw inputs + weights
    auto roundN = [&](const float* sptr, float* dptr, int n) {
        int n4 = n / 4;
        k_round<<<(n4 + 255) / 256, 256>>>((const float4*)sptr, (float4*)dptr, n4);
    };
    roundN(x,   rx,  Bc * Dc * Nc);
    roundN(src, rs,  Bc * Dc * Nc);
    roundN(Wq,  rWq, Dc * Dc);
    roundN(Wk,  rWk, Dc * Dc);
    roundN(Wv,  rWv, Dc * Dc);
    roundN(Wm,  rWm, Dc * Dc);
    roundN(W1,  rW1, 4 * Dc * Dc);
    roundN(W2,  rW2, 2 * Dc * Dc);

    // fused Q/K/V projections
    k_qkv_mma<<<dim3(Nc / 128, Dc / 64, Bc * 3), 256, CONV_SMEM_BYTES>>>(
        rWq, bq, rWk, bk, rWv, bv, rx, rs, q, k, v);

    // fused attention
    k_flash<<<dim3(Nc / 64, Bc * Hc), 128, FLASH_SMEM_BYTES>>>(q, k, v, edge, msg);

    // merge heads (output rounded: consumed by W1 via cp.async)
    k_conv_mma<<<dim3(Nc / 128, Dc / 64, Bc), 256, CONV_SMEM_BYTES>>>(
        rWm, bm, msg, nullptr, message, Dc, Dc, 0, 0, 1);

    // MLP on concat([x, message])
    k_conv_mma<<<dim3(Nc / 128, 2 * Dc / 64, Bc), 256, CONV_SMEM_BYTES>>>(
        rW1, b1, rx, message, h1, 2 * Dc, Dc, Dc, 1, 1);
    k_conv_mma<<<dim3(Nc / 128, Dc / 64, Bc), 256, CONV_SMEM_BYTES>>>(
        rW2, b2, h1, nullptr, (float*)d_out, Dc, 2 * Dc, 0, 0, 0);
}

// round 9
// speedup vs baseline: 3.6684x; 1.0968x over previous
#include <cuda_runtime.h>
#include <cuda_bf16.h>
#include <cstdint>
#include <cstddef>

// Problem constants
#define Bc 4
#define Dc 256
#define Nc 2048
#define Hc 4
#define HD 64   // head dim

// ---------------------------------------------------------------------------
// Scratch (static device arrays; allocation APIs are forbidden)
// ---------------------------------------------------------------------------
__device__ float g_q[(size_t)Bc * Dc * Nc];
__device__ float g_k[(size_t)Bc * Dc * Nc];
__device__ float g_v[(size_t)Bc * Dc * Nc];
__device__ float g_msg[(size_t)Bc * Dc * Nc];
__device__ float g_message[(size_t)Bc * Dc * Nc];
__device__ float g_h1[(size_t)Bc * 2 * Dc * Nc];
// tf32-rounded copies (conv cp.async is conversion-free AND lossless)
__device__ float g_rx[(size_t)Bc * Dc * Nc];
__device__ float g_rs[(size_t)Bc * Dc * Nc];
__device__ float g_rWq[Dc * Dc];
__device__ float g_rWk[Dc * Dc];
__device__ float g_rWv[Dc * Dc];
__device__ float g_rWm[Dc * Dc];
__device__ float g_rW1[2 * Dc * 2 * Dc];
__device__ float g_rW2[Dc * 2 * Dc];

// ---------------------------------------------------------------------------
// Fast exp: FMA polynomial
// ---------------------------------------------------------------------------
__device__ __forceinline__ float fexp(float x) {
    x = fmaxf(x, -87.0f);
    float t  = fmaf(x, 1.4426950408889634f, 12582912.0f);
    float fi = t - 12582912.0f;
    float f  = fmaf(x, 1.4426950408889634f, -fi);
    float p  = 1.3333558e-3f;
    p = fmaf(p, f, 9.6181291e-3f);
    p = fmaf(p, f, 5.5504109e-2f);
    p = fmaf(p, f, 2.4022651e-1f);
    p = fmaf(p, f, 6.9314718e-1f);
    p = fmaf(p, f, 1.0f);
    int e = (int)fi;
    return p * __int_as_float((e + 127) << 23);
}

// ---------------------------------------------------------------------------
// Tensor-core / async-copy helpers
// ---------------------------------------------------------------------------
__device__ __forceinline__ uint32_t f2tf(float x) {
    uint32_t r;
    asm("cvt.rna.tf32.f32 %0, %1;" : "=r"(r) : "f"(x));
    return r;
}
__device__ __forceinline__ float f2tf_f(float x) {
    return __uint_as_float(f2tf(x));
}
__device__ __forceinline__ void mma_tf32(float (&d)[4], const uint32_t (&a)[4],
                                         uint32_t b0, uint32_t b1) {
    asm volatile(
        "mma.sync.aligned.m16n8k8.row.col.f32.tf32.tf32.f32 "
        "{%0,%1,%2,%3}, {%4,%5,%6,%7}, {%8,%9}, {%0,%1,%2,%3};\n"
        : "+f"(d[0]), "+f"(d[1]), "+f"(d[2]), "+f"(d[3])
        : "r"(a[0]), "r"(a[1]), "r"(a[2]), "r"(a[3]), "r"(b0), "r"(b1));
}
__device__ __forceinline__ void cpa16(uint32_t s, const float* g) {
    asm volatile("cp.async.cg.shared.global [%0], [%1], 16;" :: "r"(s), "l"(g) : "memory");
}
__device__ __forceinline__ void cpa_commit() {
    asm volatile("cp.async.commit_group;" ::: "memory");
}
__device__ __forceinline__ void cpa_wait1() {
    asm volatile("cp.async.wait_group 1;" ::: "memory");
}
__device__ __forceinline__ void cpa_wait2() {
    asm volatile("cp.async.wait_group 2;" ::: "memory");
}

// ---------------------------------------------------------------------------
// Fused tf32 pre-round of all raw inputs + weights (one launch).
// Segment sizes in float4: x 524288, src 524288, Wq/Wk/Wv/Wm 16384 each,
// W1 65536, W2 32768. Total 1212416 float4 -> grid 4736 x 256.
// ---------------------------------------------------------------------------
__global__ void __launch_bounds__(256)
k_round_all(const float4* __restrict__ x,  const float4* __restrict__ s,
            const float4* __restrict__ wq, const float4* __restrict__ wk,
            const float4* __restrict__ wv, const float4* __restrict__ wm,
            const float4* __restrict__ w1, const float4* __restrict__ w2,
            float4* __restrict__ rx,  float4* __restrict__ rs,
            float4* __restrict__ rwq, float4* __restrict__ rwk,
            float4* __restrict__ rwv, float4* __restrict__ rwm,
            float4* __restrict__ rw1, float4* __restrict__ rw2)
{
    int i = blockIdx.x * blockDim.x + threadIdx.x;
    const float4* sp; float4* dp; int off;
    if      (i < 524288)  { sp = x;  dp = rx;  off = i; }
    else if (i < 1048576) { sp = s;  dp = rs;  off = i - 524288; }
    else if (i < 1064960) { sp = wq; dp = rwq; off = i - 1048576; }
    else if (i < 1081344) { sp = wk; dp = rwk; off = i - 1064960; }
    else if (i < 1097728) { sp = wv; dp = rwv; off = i - 1081344; }
    else if (i < 1114112) { sp = wm; dp = rwm; off = i - 1097728; }
    else if (i < 1179648) { sp = w1; dp = rw1; off = i - 1114112; }
    else if (i < 1212416) { sp = w2; dp = rw2; off = i - 1179648; }
    else return;
    float4 t = sp[off];
    t.x = f2tf_f(t.x); t.y = f2tf_f(t.y);
    t.z = f2tf_f(t.z); t.w = f2tf_f(t.w);
    dp[off] = t;
}

// ---------------------------------------------------------------------------
// conv1x1 on tensor cores (round-8 design, unchanged): 4-stage cp.async,
// one sync per K-step, all inputs exactly-tf32.
// ---------------------------------------------------------------------------
#define CWST 20
#define CXST 136
#define CBUF (64 * CWST + 16 * CXST)
#define CONV_SMEM_BYTES (4 * CBUF * 4)

__device__ __forceinline__ void conv_tile_mma(
    const float* __restrict__ W, const float* __restrict__ bias,
    const float* __restrict__ X1b, const float* __restrict__ X2b,
    float* __restrict__ Yb, int Din, int D1, int relu, int round_out,
    int o0, int n0, float* smbase)
{
    const int tid  = threadIdx.x;
    const int warp = tid >> 5, lane = tid & 31;
    const int g  = lane >> 2, tc = lane & 3;
    const int wo = (warp & 1) * 32;
    const int wn = (warp >> 1) * 32;
    const int niter = Din >> 4;

    float* stg[4] = {smbase, smbase + CBUF, smbase + 2 * CBUF, smbase + 3 * CBUF};
    const int wrow = tid >> 2, wkc = (tid & 3) * 4;

    auto issue = [&](int k0, float* buf) {
        uint32_t bu = (uint32_t)__cvta_generic_to_shared(buf);
        cpa16(bu + (uint32_t)(wrow * CWST + wkc) * 4,
              W + (size_t)(o0 + wrow) * Din + k0 + wkc);
        #pragma unroll
        for (int i = 0; i < 2; i++) {
            int c   = tid + 256 * i;
            int row = c >> 5, col = (c & 31) * 4;
            int ch  = k0 + row;
            const float* s = (ch < D1) ? (X1b + (size_t)ch * Nc)
                                       : (X2b + (size_t)(ch - D1) * Nc);
            cpa16(bu + (uint32_t)(64 * CWST + row * CXST + col) * 4, s + n0 + col);
        }
        cpa_commit();
    };

    issue(0, stg[0]);
    issue(16, stg[1]);
    issue(32, stg[2]);

    float d[2][4][4] = {};

    for (int it = 0; it < niter; it++) {
        cpa_wait2();
        __syncthreads();
        const float* Wst = stg[it & 3];
        const float* Xst = Wst + 64 * CWST;

        #pragma unroll
        for (int ks = 0; ks < 2; ks++) {
            uint32_t a[2][4];
            #pragma unroll
            for (int mt = 0; mt < 2; mt++) {
                const float* wr = &Wst[(wo + 16 * mt + g) * CWST + 8 * ks + tc];
                a[mt][0] = __float_as_uint(wr[0]);
                a[mt][1] = __float_as_uint(wr[8 * CWST]);
                a[mt][2] = __float_as_uint(wr[4]);
                a[mt][3] = __float_as_uint(wr[8 * CWST + 4]);
            }
            #pragma unroll
            for (int jt = 0; jt < 4; jt++) {
                const float* xr = &Xst[(8 * ks + tc) * CXST + wn + 8 * jt + g];
                uint32_t b0 = __float_as_uint(xr[0]);
                uint32_t b1 = __float_as_uint(xr[4 * CXST]);
                mma_tf32(d[0][jt], a[0], b0, b1);
                mma_tf32(d[1][jt], a[1], b0, b1);
            }
        }

        int nit = it + 3;
        if (nit < niter) issue(nit * 16, stg[nit & 3]);
        else             cpa_commit();
    }

    #pragma unroll
    for (int mt = 0; mt < 2; mt++) {
        int or0 = o0 + wo + 16 * mt + g;
        int or1 = or0 + 8;
        float bv0 = bias[or0], bv1 = bias[or1];
        #pragma unroll
        for (int jt = 0; jt < 4; jt++) {
            int nn = n0 + wn + 8 * jt + 2 * tc;
            float2 r0 = make_float2(d[mt][jt][0] + bv0, d[mt][jt][1] + bv0);
            float2 r1 = make_float2(d[mt][jt][2] + bv1, d[mt][jt][3] + bv1);
            if (relu) {
                r0.x = fmaxf(r0.x, 0.f); r0.y = fmaxf(r0.y, 0.f);
                r1.x = fmaxf(r1.x, 0.f); r1.y = fmaxf(r1.y, 0.f);
            }
            if (round_out) {
                r0.x = f2tf_f(r0.x); r0.y = f2tf_f(r0.y);
                r1.x = f2tf_f(r1.x); r1.y = f2tf_f(r1.y);
            }
            *(float2*)&Yb[(size_t)or0 * Nc + nn] = r0;
            *(float2*)&Yb[(size_t)or1 * Nc + nn] = r1;
        }
    }
}

__global__ void __launch_bounds__(256)
k_conv_mma(const float* __restrict__ W, const float* __restrict__ bias,
           const float* __restrict__ X1, const float* __restrict__ X2,
           float* __restrict__ Y, int Dout, int D1, int D2, int relu,
           int round_out)
{
    extern __shared__ float smc[];
    int b = blockIdx.z;
    conv_tile_mma(W, bias,
                  X1 + (size_t)b * D1 * Nc,
                  X2 ? (X2 + (size_t)b * D2 * Nc) : nullptr,
                  Y + (size_t)b * Dout * Nc,
                  D1 + D2, D1, relu, round_out,
                  blockIdx.y * 64, blockIdx.x * 128, smc);
}

__global__ void __launch_bounds__(256)
k_qkv_mma(const float* __restrict__ Wq, const float* __restrict__ bq,
          const float* __restrict__ Wk, const float* __restrict__ bk,
          const float* __restrict__ Wv, const float* __restrict__ bv,
          const float* __restrict__ x, const float* __restrict__ src,
          float* __restrict__ q, float* __restrict__ k, float* __restrict__ v)
{
    extern __shared__ float smc[];
    int z = blockIdx.z;
    int b = z / 3, which = z % 3;
    const float* W; const float* bias; const float* X; float* Y;
    if (which == 0)      { W = Wq; bias = bq; X = x;   Y = q; }
    else if (which == 1) { W = Wk; bias = bk; X = src; Y = k; }
    else                 { W = Wv; bias = bv; X = src; Y = v; }
    conv_tile_mma(W, bias, X + (size_t)b * Dc * Nc, nullptr,
                  Y + (size_t)b * Dc * Nc, Dc, Dc, 0, 1,
                  blockIdx.y * 64, blockIdx.x * 128, smc);
}

// ---------------------------------------------------------------------------
// Flash attention v3: register-resident P via S-column permutation +
// double-buffered whole-tile prefetch (K+E+V one commit group, 2 syncs/tile).
//
// Permutation: feeding K's B-operand column position c with source column
// sigma(c) = c/2 + (c&1)*4 makes the S d-fragment hold source cols
// {8j+tc, 8j+tc+4} — exactly the A-fragment layout PV needs, so P stays in
// registers. PV computes O[n][dd] = P*V with B-frags from the natural
// [dd][m] V tile. Z reduction is layout-invariant (full-row sums).
// Bank strides: K/E 72, V 68 -> all fragment loads conflict-free.
// grid: (N/64, B*H), 128 threads
// ---------------------------------------------------------------------------
#define KST 72
#define EST 72
#define VST 68
#define STAGE_FLOATS (64 * KST + 64 * EST + 64 * VST)   // 13568
#define FLASH_SMEM_BYTES (2 * STAGE_FLOATS * 4)          // 108544
#define NTILES (Nc / 64)

__global__ void __launch_bounds__(128)
k_flash(const float* __restrict__ q, const float* __restrict__ k,
        const float* __restrict__ v, const float* __restrict__ edge,
        float* __restrict__ Msg)
{
    extern __shared__ float sm[];

    const int bh = blockIdx.y;
    const int b = bh >> 2, h = bh & 3;
    const int n0 = blockIdx.x * 64;

    const int tid  = threadIdx.x;
    const int warp = tid >> 5;
    const int lane = tid & 31;
    const int g  = lane >> 2;
    const int tc = lane & 3;
    const int nw = warp * 16;                      // this warp's n-strip
    const int sg = (g >> 1) + ((g & 1) << 2);      // sigma(g)

    const float* qb = q + (size_t)b * Dc * Nc;
    const float* kb = k + (size_t)b * Dc * Nc;
    const float* vb = v + (size_t)b * Dc * Nc;
    const float* eb = edge + (size_t)b * Nc * Nc + n0 * (size_t)Nc;

    const int crow = tid >> 4;          // 0..7
    const int ccol = (tid & 15) * 4;    // 0..60

    // --- Q a-fragments, resident (layout unchanged from round 8) ---
    uint32_t qa[8][4];
    #pragma unroll
    for (int kk = 0; kk < 8; kk++) {
        int ch0 = (8 * kk + tc) * 4 + h;
        int ch1 = (8 * kk + tc + 4) * 4 + h;
        qa[kk][0] = f2tf(qb[(size_t)ch0 * Nc + n0 + nw + g]);
        qa[kk][1] = f2tf(qb[(size_t)ch0 * Nc + n0 + nw + g + 8]);
        qa[kk][2] = f2tf(qb[(size_t)ch1 * Nc + n0 + nw + g]);
        qa[kk][3] = f2tf(qb[(size_t)ch1 * Nc + n0 + nw + g + 8]);
    }

    // One commit group = K + E + V of a whole tile into stage st.
    auto issueAll = [&](int m0, int st) {
        float* base = sm + st * STAGE_FLOATS;
        uint32_t ku = (uint32_t)__cvta_generic_to_shared(base);
        uint32_t eu = ku + 64 * KST * 4;
        uint32_t vu = eu + 64 * EST * 4;
        #pragma unroll
        for (int i = 0; i < 8; i++) {
            int r = crow + 8 * i;
            cpa16(ku + (uint32_t)(r * KST + ccol) * 4,
                  kb + (size_t)(r * 4 + h) * Nc + m0 + ccol);
        }
        #pragma unroll
        for (int i = 0; i < 8; i++) {
            int r = crow + 8 * i;
            cpa16(eu + (uint32_t)(r * EST + ccol) * 4,
                  eb + (size_t)r * Nc + m0 + ccol);
        }
        #pragma unroll
        for (int i = 0; i < 8; i++) {
            int r = crow + 8 * i;
            cpa16(vu + (uint32_t)(r * VST + ccol) * 4,
                  vb + (size_t)(r * 4 + h) * Nc + m0 + ccol);
        }
        cpa_commit();
    };

    issueAll(0, 0);
    issueAll(64, 1);

    float o[8][4] = {};
    float Z0 = 0.f, Z1 = 0.f;

    for (int t = 0; t < NTILES; t++) {
        const int st = t & 1;
        const float* Ks = sm + st * STAGE_FLOATS;
        const float* Es = Ks + 64 * KST;
        const float* Vs = Es + 64 * EST;

        cpa_wait1();
        __syncthreads();   // tile t visible; prev parity fully consumed

        // --- S = Q^T K (columns permuted by sigma) ---
        float p[8][4] = {};
        #pragma unroll
        for (int kk = 0; kk < 8; kk++) {
            const float* kr0 = &Ks[(8 * kk + tc) * KST + sg];
            const float* kr1 = &Ks[(8 * kk + tc + 4) * KST + sg];
            #pragma unroll
            for (int j = 0; j < 8; j++) {
                uint32_t b0 = __float_as_uint(kr0[8 * j]);
                uint32_t b1 = __float_as_uint(kr1[8 * j]);
                mma_tf32(p[j], qa[kk], b0, b1);
            }
        }

        // --- softmax + edge, P stays in registers ---
        // p[j][0]: (row nw+g,   src col 8j+tc)    p[j][1]: (row nw+g,   8j+tc+4)
        // p[j][2]: (row nw+g+8, src col 8j+tc)    p[j][3]: (row nw+g+8, 8j+tc+4)
        #pragma unroll
        for (int j = 0; j < 8; j++) {
            float e00 = Es[(nw + g) * EST + 8 * j + tc];
            float e01 = Es[(nw + g) * EST + 8 * j + tc + 4];
            float e10 = Es[(nw + g + 8) * EST + 8 * j + tc];
            float e11 = Es[(nw + g + 8) * EST + 8 * j + tc + 4];
            float p00 = fexp(p[j][0] * 0.125f);
            float p01 = fexp(p[j][1] * 0.125f);
            float p10 = fexp(p[j][2] * 0.125f);
            float p11 = fexp(p[j][3] * 0.125f);
            Z0 += p00 + p01;
            Z1 += p10 + p11;
            p[j][0] = f2tf_f(p00 * e00);
            p[j][1] = f2tf_f(p01 * e01);
            p[j][2] = f2tf_f(p10 * e10);
            p[j][3] = f2tf_f(p11 * e11);
        }

        // --- O[n][dd] += P * V  (A=P regs, B=V from [dd][m] tile) ---
        #pragma unroll
        for (int kk = 0; kk < 8; kk++) {
            uint32_t a[4] = { __float_as_uint(p[kk][0]), __float_as_uint(p[kk][2]),
                              __float_as_uint(p[kk][1]), __float_as_uint(p[kk][3]) };
            #pragma unroll
            for (int jd = 0; jd < 8; jd++) {
                uint32_t b0 = __float_as_uint(Vs[(8 * jd + g) * VST + 8 * kk + tc]);
                uint32_t b1 = __float_as_uint(Vs[(8 * jd + g) * VST + 8 * kk + tc + 4]);
                mma_tf32(o[jd], a, b0, b1);
            }
        }

        __syncthreads();   // all warps done with stage st
        int tn = t + 2;
        if (tn < NTILES) issueAll(tn * 64, st);
        else             cpa_commit();       // keep group accounting; no stray writes
    }

    // --- epilogue: quad-reduce Z (rows are thread-local now), write O/Z ---
    Z0 += __shfl_xor_sync(0xffffffffu, Z0, 1);
    Z0 += __shfl_xor_sync(0xffffffffu, Z0, 2);
    Z1 += __shfl_xor_sync(0xffffffffu, Z1, 1);
    Z1 += __shfl_xor_sync(0xffffffffu, Z1, 2);
    float zi0 = 1.0f / Z0;
    float zi1 = 1.0f / Z1;

    #pragma unroll
    for (int jd = 0; jd < 8; jd++) {
        int dd0 = 8 * jd + 2 * tc;
        int dd1 = dd0 + 1;
        float* m0p = Msg + ((size_t)b * Dc + dd0 * 4 + h) * Nc + n0 + nw;
        float* m1p = Msg + ((size_t)b * Dc + dd1 * 4 + h) * Nc + n0 + nw;
        m0p[g]     = f2tf_f(o[jd][0] * zi0);
        m1p[g]     = f2tf_f(o[jd][1] * zi0);
        m0p[g + 8] = f2tf_f(o[jd][2] * zi1);
        m1p[g + 8] = f2tf_f(o[jd][3] * zi1);
    }
}

// ---------------------------------------------------------------------------
// Launch
// ---------------------------------------------------------------------------
extern "C" void kernel_launch(void* const* d_in, const int* in_sizes, int n_in,
                              void* d_out, int out_size)
{
    const float* x    = (const float*)d_in[0];
    const float* src  = (const float*)d_in[1];
    const float* edge = (const float*)d_in[2];
    const float* Wq = (const float*)d_in[3];  const float* bq = (const float*)d_in[4];
    const float* Wk = (const float*)d_in[5];  const float* bk = (const float*)d_in[6];
    const float* Wv = (const float*)d_in[7];  const float* bv = (const float*)d_in[8];
    const float* Wm = (const float*)d_in[9];  const float* bm = (const float*)d_in[10];
    const float* W1 = (const float*)d_in[11]; const float* b1 = (const float*)d_in[12];
    const float* W2 = (const float*)d_in[13]; const float* b2 = (const float*)d_in[14];

    float *q, *k, *v, *msg, *message, *h1;
    float *rx, *rs, *rWq, *rWk, *rWv, *rWm, *rW1, *rW2;
    cudaGetSymbolAddress((void**)&q,       g_q);
    cudaGetSymbolAddress((void**)&k,       g_k);
    cudaGetSymbolAddress((void**)&v,       g_v);
    cudaGetSymbolAddress((void**)&msg,     g_msg);
    cudaGetSymbolAddress((void**)&message, g_message);
    cudaGetSymbolAddress((void**)&h1,      g_h1);
    cudaGetSymbolAddress((void**)&rx,      g_rx);
    cudaGetSymbolAddress((void**)&rs,      g_rs);
    cudaGetSymbolAddress((void**)&rWq,     g_rWq);
    cudaGetSymbolAddress((void**)&rWk,     g_rWk);
    cudaGetSymbolAddress((void**)&rWv,     g_rWv);
    cudaGetSymbolAddress((void**)&rWm,     g_rWm);
    cudaGetSymbolAddress((void**)&rW1,     g_rW1);
    cudaGetSymbolAddress((void**)&rW2,     g_rW2);

    cudaFuncSetAttribute(k_flash, cudaFuncAttributeMaxDynamicSharedMemorySize,
                         FLASH_SMEM_BYTES);
    cudaFuncSetAttribute(k_conv_mma, cudaFuncAttributeMaxDynamicSharedMemorySize,
                         CONV_SMEM_BYTES);
    cudaFuncSetAttribute(k_qkv_mma, cudaFuncAttributeMaxDynamicSharedMemorySize,
                         CONV_SMEM_BYTES);

    // single fused tf32 pre-round (x, src, all weights)
    k_round_all<<<4736, 256>>>(
        (const float4*)x,  (const float4*)src,
        (const float4*)Wq, (const float4*)Wk,
        (const float4*)Wv, (const float4*)Wm,
        (const float4*)W1, (const float4*)W2,
        (float4*)rx,  (float4*)rs,
        (float4*)rWq, (float4*)rWk,
        (float4*)rWv, (float4*)rWm,
        (float4*)rW1, (float4*)rW2);

    // fused Q/K/V projections
    k_qkv_mma<<<dim3(Nc / 128, Dc / 64, Bc * 3), 256, CONV_SMEM_BYTES>>>(
        rWq, bq, rWk, bk, rWv, bv, rx, rs, q, k, v);

    // fused attention (register-resident P, double-buffered tiles)
    k_flash<<<dim3(Nc / 64, Bc * Hc), 128, FLASH_SMEM_BYTES>>>(q, k, v, edge, msg);

    // merge heads (output rounded: consumed by W1 via cp.async)
    k_conv_mma<<<dim3(Nc / 128, Dc / 64, Bc), 256, CONV_SMEM_BYTES>>>(
        rWm, bm, msg, nullptr, message, Dc, Dc, 0, 0, 1);

    // MLP on concat([x, message])
    k_conv_mma<<<dim3(Nc / 128, 2 * Dc / 64, Bc), 256, CONV_SMEM_BYTES>>>(
        rW1, b1, rx, message, h1, 2 * Dc, Dc, Dc, 1, 1);
    k_conv_mma<<<dim3(Nc / 128, Dc / 64, Bc), 256, CONV_SMEM_BYTES>>>(
        rW2, b2, h1, nullptr, (float*)d_out, Dc, 2 * Dc, 0, 0, 0);
}

// round 10
// speedup vs baseline: 3.7164x; 1.0131x over previous
#include <cuda_runtime.h>
#include <cuda_bf16.h>
#include <cstdint>
#include <cstddef>

// Problem constants
#define Bc 4
#define Dc 256
#define Nc 2048
#define Hc 4
#define HD 64   // head dim

// ---------------------------------------------------------------------------
// Scratch (static device arrays; allocation APIs are forbidden)
// ---------------------------------------------------------------------------
__device__ float g_q[(size_t)Bc * Dc * Nc];
__device__ float g_k[(size_t)Bc * Dc * Nc];
__device__ float g_v[(size_t)Bc * Dc * Nc];
__device__ float g_msg[(size_t)Bc * Dc * Nc];
__device__ float g_message[(size_t)Bc * Dc * Nc];
__device__ float g_h1[(size_t)Bc * 2 * Dc * Nc];
// split-K attention partials
__device__ float g_po[2 * (size_t)Bc * Dc * Nc];
__device__ float g_pz[2 * (size_t)Bc * Hc * Nc];
// tf32-rounded copies (conv cp.async is conversion-free AND lossless)
__device__ float g_rx[(size_t)Bc * Dc * Nc];
__device__ float g_rs[(size_t)Bc * Dc * Nc];
__device__ float g_rWq[Dc * Dc];
__device__ float g_rWk[Dc * Dc];
__device__ float g_rWv[Dc * Dc];
__device__ float g_rWm[Dc * Dc];
__device__ float g_rW1[2 * Dc * 2 * Dc];
__device__ float g_rW2[Dc * 2 * Dc];

#define OSZ ((size_t)Bc * Dc * Nc)
#define ZSZ ((size_t)Bc * Hc * Nc)

// ---------------------------------------------------------------------------
// Fast exp: FMA polynomial
// ---------------------------------------------------------------------------
__device__ __forceinline__ float fexp(float x) {
    x = fmaxf(x, -87.0f);
    float t  = fmaf(x, 1.4426950408889634f, 12582912.0f);
    float fi = t - 12582912.0f;
    float f  = fmaf(x, 1.4426950408889634f, -fi);
    float p  = 1.3333558e-3f;
    p = fmaf(p, f, 9.6181291e-3f);
    p = fmaf(p, f, 5.5504109e-2f);
    p = fmaf(p, f, 2.4022651e-1f);
    p = fmaf(p, f, 6.9314718e-1f);
    p = fmaf(p, f, 1.0f);
    int e = (int)fi;
    return p * __int_as_float((e + 127) << 23);
}

// ---------------------------------------------------------------------------
// Tensor-core / async-copy helpers
// ---------------------------------------------------------------------------
__device__ __forceinline__ uint32_t f2tf(float x) {
    uint32_t r;
    asm("cvt.rna.tf32.f32 %0, %1;" : "=r"(r) : "f"(x));
    return r;
}
__device__ __forceinline__ float f2tf_f(float x) {
    return __uint_as_float(f2tf(x));
}
__device__ __forceinline__ void mma_tf32(float (&d)[4], const uint32_t (&a)[4],
                                         uint32_t b0, uint32_t b1) {
    asm volatile(
        "mma.sync.aligned.m16n8k8.row.col.f32.tf32.tf32.f32 "
        "{%0,%1,%2,%3}, {%4,%5,%6,%7}, {%8,%9}, {%0,%1,%2,%3};\n"
        : "+f"(d[0]), "+f"(d[1]), "+f"(d[2]), "+f"(d[3])
        : "r"(a[0]), "r"(a[1]), "r"(a[2]), "r"(a[3]), "r"(b0), "r"(b1));
}
__device__ __forceinline__ void cpa16(uint32_t s, const float* g) {
    asm volatile("cp.async.cg.shared.global [%0], [%1], 16;" :: "r"(s), "l"(g) : "memory");
}
__device__ __forceinline__ void cpa_commit() {
    asm volatile("cp.async.commit_group;" ::: "memory");
}
__device__ __forceinline__ void cpa_wait1() {
    asm volatile("cp.async.wait_group 1;" ::: "memory");
}
__device__ __forceinline__ void cpa_wait2() {
    asm volatile("cp.async.wait_group 2;" ::: "memory");
}

// ---------------------------------------------------------------------------
// Fused tf32 pre-round of all raw inputs + weights (one launch).
// ---------------------------------------------------------------------------
__global__ void __launch_bounds__(256)
k_round_all(const float4* __restrict__ x,  const float4* __restrict__ s,
            const float4* __restrict__ wq, const float4* __restrict__ wk,
            const float4* __restrict__ wv, const float4* __restrict__ wm,
            const float4* __restrict__ w1, const float4* __restrict__ w2,
            float4* __restrict__ rx,  float4* __restrict__ rs,
            float4* __restrict__ rwq, float4* __restrict__ rwk,
            float4* __restrict__ rwv, float4* __restrict__ rwm,
            float4* __restrict__ rw1, float4* __restrict__ rw2)
{
    int i = blockIdx.x * blockDim.x + threadIdx.x;
    const float4* sp; float4* dp; int off;
    if      (i < 524288)  { sp = x;  dp = rx;  off = i; }
    else if (i < 1048576) { sp = s;  dp = rs;  off = i - 524288; }
    else if (i < 1064960) { sp = wq; dp = rwq; off = i - 1048576; }
    else if (i < 1081344) { sp = wk; dp = rwk; off = i - 1064960; }
    else if (i < 1097728) { sp = wv; dp = rwv; off = i - 1081344; }
    else if (i < 1114112) { sp = wm; dp = rwm; off = i - 1097728; }
    else if (i < 1179648) { sp = w1; dp = rw1; off = i - 1114112; }
    else if (i < 1212416) { sp = w2; dp = rw2; off = i - 1179648; }
    else return;
    float4 t = sp[off];
    t.x = f2tf_f(t.x); t.y = f2tf_f(t.y);
    t.z = f2tf_f(t.z); t.w = f2tf_f(t.w);
    dp[off] = t;
}

// ---------------------------------------------------------------------------
// conv1x1 on tensor cores (round-8 design, unchanged)
// ---------------------------------------------------------------------------
#define CWST 20
#define CXST 136
#define CBUF (64 * CWST + 16 * CXST)
#define CONV_SMEM_BYTES (4 * CBUF * 4)

__device__ __forceinline__ void conv_tile_mma(
    const float* __restrict__ W, const float* __restrict__ bias,
    const float* __restrict__ X1b, const float* __restrict__ X2b,
    float* __restrict__ Yb, int Din, int D1, int relu, int round_out,
    int o0, int n0, float* smbase)
{
    const int tid  = threadIdx.x;
    const int warp = tid >> 5, lane = tid & 31;
    const int g  = lane >> 2, tc = lane & 3;
    const int wo = (warp & 1) * 32;
    const int wn = (warp >> 1) * 32;
    const int niter = Din >> 4;

    float* stg[4] = {smbase, smbase + CBUF, smbase + 2 * CBUF, smbase + 3 * CBUF};
    const int wrow = tid >> 2, wkc = (tid & 3) * 4;

    auto issue = [&](int k0, float* buf) {
        uint32_t bu = (uint32_t)__cvta_generic_to_shared(buf);
        cpa16(bu + (uint32_t)(wrow * CWST + wkc) * 4,
              W + (size_t)(o0 + wrow) * Din + k0 + wkc);
        #pragma unroll
        for (int i = 0; i < 2; i++) {
            int c   = tid + 256 * i;
            int row = c >> 5, col = (c & 31) * 4;
            int ch  = k0 + row;
            const float* s = (ch < D1) ? (X1b + (size_t)ch * Nc)
                                       : (X2b + (size_t)(ch - D1) * Nc);
            cpa16(bu + (uint32_t)(64 * CWST + row * CXST + col) * 4, s + n0 + col);
        }
        cpa_commit();
    };

    issue(0, stg[0]);
    issue(16, stg[1]);
    issue(32, stg[2]);

    float d[2][4][4] = {};

    for (int it = 0; it < niter; it++) {
        cpa_wait2();
        __syncthreads();
        const float* Wst = stg[it & 3];
        const float* Xst = Wst + 64 * CWST;

        #pragma unroll
        for (int ks = 0; ks < 2; ks++) {
            uint32_t a[2][4];
            #pragma unroll
            for (int mt = 0; mt < 2; mt++) {
                const float* wr = &Wst[(wo + 16 * mt + g) * CWST + 8 * ks + tc];
                a[mt][0] = __float_as_uint(wr[0]);
                a[mt][1] = __float_as_uint(wr[8 * CWST]);
                a[mt][2] = __float_as_uint(wr[4]);
                a[mt][3] = __float_as_uint(wr[8 * CWST + 4]);
            }
            #pragma unroll
            for (int jt = 0; jt < 4; jt++) {
                const float* xr = &Xst[(8 * ks + tc) * CXST + wn + 8 * jt + g];
                uint32_t b0 = __float_as_uint(xr[0]);
                uint32_t b1 = __float_as_uint(xr[4 * CXST]);
                mma_tf32(d[0][jt], a[0], b0, b1);
                mma_tf32(d[1][jt], a[1], b0, b1);
            }
        }

        int nit = it + 3;
        if (nit < niter) issue(nit * 16, stg[nit & 3]);
        else             cpa_commit();
    }

    #pragma unroll
    for (int mt = 0; mt < 2; mt++) {
        int or0 = o0 + wo + 16 * mt + g;
        int or1 = or0 + 8;
        float bv0 = bias[or0], bv1 = bias[or1];
        #pragma unroll
        for (int jt = 0; jt < 4; jt++) {
            int nn = n0 + wn + 8 * jt + 2 * tc;
            float2 r0 = make_float2(d[mt][jt][0] + bv0, d[mt][jt][1] + bv0);
            float2 r1 = make_float2(d[mt][jt][2] + bv1, d[mt][jt][3] + bv1);
            if (relu) {
                r0.x = fmaxf(r0.x, 0.f); r0.y = fmaxf(r0.y, 0.f);
                r1.x = fmaxf(r1.x, 0.f); r1.y = fmaxf(r1.y, 0.f);
            }
            if (round_out) {
                r0.x = f2tf_f(r0.x); r0.y = f2tf_f(r0.y);
                r1.x = f2tf_f(r1.x); r1.y = f2tf_f(r1.y);
            }
            *(float2*)&Yb[(size_t)or0 * Nc + nn] = r0;
            *(float2*)&Yb[(size_t)or1 * Nc + nn] = r1;
        }
    }
}

__global__ void __launch_bounds__(256)
k_conv_mma(const float* __restrict__ W, const float* __restrict__ bias,
           const float* __restrict__ X1, const float* __restrict__ X2,
           float* __restrict__ Y, int Dout, int D1, int D2, int relu,
           int round_out)
{
    extern __shared__ float smc[];
    int b = blockIdx.z;
    conv_tile_mma(W, bias,
                  X1 + (size_t)b * D1 * Nc,
                  X2 ? (X2 + (size_t)b * D2 * Nc) : nullptr,
                  Y + (size_t)b * Dout * Nc,
                  D1 + D2, D1, relu, round_out,
                  blockIdx.y * 64, blockIdx.x * 128, smc);
}

__global__ void __launch_bounds__(256)
k_qkv_mma(const float* __restrict__ Wq, const float* __restrict__ bq,
          const float* __restrict__ Wk, const float* __restrict__ bk,
          const float* __restrict__ Wv, const float* __restrict__ bv,
          const float* __restrict__ x, const float* __restrict__ src,
          float* __restrict__ q, float* __restrict__ k, float* __restrict__ v)
{
    extern __shared__ float smc[];
    int z = blockIdx.z;
    int b = z / 3, which = z % 3;
    const float* W; const float* bias; const float* X; float* Y;
    if (which == 0)      { W = Wq; bias = bq; X = x;   Y = q; }
    else if (which == 1) { W = Wk; bias = bk; X = src; Y = k; }
    else                 { W = Wv; bias = bv; X = src; Y = v; }
    conv_tile_mma(W, bias, X + (size_t)b * Dc * Nc, nullptr,
                  Y + (size_t)b * Dc * Nc, Dc, Dc, 0, 1,
                  blockIdx.y * 64, blockIdx.x * 128, smc);
}

// ---------------------------------------------------------------------------
// Flash attention v4: split-K (2 halves via blockIdx.z) + edge via direct
// LDG (out of smem). Stage = K(64x72)+V(64x68) -> 71.7KB -> 3 blocks/SM.
// Max-free softmax => partials combine as (O0+O1)/(Z0+Z1) in k_combine.
// grid: (N/64, B*H, 2), 128 threads
// ---------------------------------------------------------------------------
#define KST 72
#define VST 68
#define STAGE_FLOATS (64 * KST + 64 * VST)      // 8960
#define FLASH_SMEM_BYTES (2 * STAGE_FLOATS * 4) // 71680
#define NTILES (Nc / 64)
#define HALF_TILES (NTILES / 2)

__global__ void __launch_bounds__(128, 3)
k_flash(const float* __restrict__ q, const float* __restrict__ k,
        const float* __restrict__ v, const float* __restrict__ edge,
        float* __restrict__ Po, float* __restrict__ Pz)
{
    extern __shared__ float sm[];

    const int bh = blockIdx.y;
    const int b = bh >> 2, h = bh & 3;
    const int n0 = blockIdx.x * 64;
    const int zh = blockIdx.z;
    const int t0 = zh * HALF_TILES;
    Po += (size_t)zh * OSZ;
    Pz += (size_t)zh * ZSZ;

    const int tid  = threadIdx.x;
    const int warp = tid >> 5;
    const int lane = tid & 31;
    const int g  = lane >> 2;
    const int tc = lane & 3;
    const int nw = warp * 16;
    const int sg = (g >> 1) + ((g & 1) << 2);   // sigma(g)

    const float* qb = q + (size_t)b * Dc * Nc;
    const float* kb = k + (size_t)b * Dc * Nc;
    const float* vb = v + (size_t)b * Dc * Nc;
    const float* er0 = edge + ((size_t)b * Nc + n0 + nw + g) * Nc;
    const float* er1 = er0 + (size_t)8 * Nc;

    const int crow = tid >> 4;
    const int ccol = (tid & 15) * 4;

    uint32_t qa[8][4];
    #pragma unroll
    for (int kk = 0; kk < 8; kk++) {
        int ch0 = (8 * kk + tc) * 4 + h;
        int ch1 = (8 * kk + tc + 4) * 4 + h;
        qa[kk][0] = f2tf(qb[(size_t)ch0 * Nc + n0 + nw + g]);
        qa[kk][1] = f2tf(qb[(size_t)ch0 * Nc + n0 + nw + g + 8]);
        qa[kk][2] = f2tf(qb[(size_t)ch1 * Nc + n0 + nw + g]);
        qa[kk][3] = f2tf(qb[(size_t)ch1 * Nc + n0 + nw + g + 8]);
    }

    auto issueKV = [&](int m0, int st) {
        float* base = sm + st * STAGE_FLOATS;
        uint32_t ku = (uint32_t)__cvta_generic_to_shared(base);
        uint32_t vu = ku + 64 * KST * 4;
        #pragma unroll
        for (int i = 0; i < 8; i++) {
            int r = crow + 8 * i;
            cpa16(ku + (uint32_t)(r * KST + ccol) * 4,
                  kb + (size_t)(r * 4 + h) * Nc + m0 + ccol);
        }
        #pragma unroll
        for (int i = 0; i < 8; i++) {
            int r = crow + 8 * i;
            cpa16(vu + (uint32_t)(r * VST + ccol) * 4,
                  vb + (size_t)(r * 4 + h) * Nc + m0 + ccol);
        }
        cpa_commit();
    };

    issueKV(t0 * 64, 0);
    issueKV(t0 * 64 + 64, 1);

    float o[8][4] = {};
    float Z0 = 0.f, Z1 = 0.f;

    for (int t = t0; t < t0 + HALF_TILES; t++) {
        const int st = t & 1;
        const float* Ks = sm + st * STAGE_FLOATS;
        const float* Vs = Ks + 64 * KST;
        const int m0 = t * 64;

        // edge prefetch into registers (consumed after S GEMM)
        float er[8][4];
        #pragma unroll
        for (int j = 0; j < 8; j++) {
            er[j][0] = er0[m0 + 8 * j + tc];
            er[j][1] = er0[m0 + 8 * j + tc + 4];
            er[j][2] = er1[m0 + 8 * j + tc];
            er[j][3] = er1[m0 + 8 * j + tc + 4];
        }

        cpa_wait1();
        __syncthreads();

        // --- S = Q^T K (columns permuted by sigma) ---
        float p[8][4] = {};
        #pragma unroll
        for (int kk = 0; kk < 8; kk++) {
            const float* kr0 = &Ks[(8 * kk + tc) * KST + sg];
            const float* kr1 = &Ks[(8 * kk + tc + 4) * KST + sg];
            #pragma unroll
            for (int j = 0; j < 8; j++) {
                uint32_t b0 = __float_as_uint(kr0[8 * j]);
                uint32_t b1 = __float_as_uint(kr1[8 * j]);
                mma_tf32(p[j], qa[kk], b0, b1);
            }
        }

        // --- softmax + edge, P in registers ---
        #pragma unroll
        for (int j = 0; j < 8; j++) {
            float p00 = fexp(p[j][0] * 0.125f);
            float p01 = fexp(p[j][1] * 0.125f);
            float p10 = fexp(p[j][2] * 0.125f);
            float p11 = fexp(p[j][3] * 0.125f);
            Z0 += p00 + p01;
            Z1 += p10 + p11;
            p[j][0] = f2tf_f(p00 * er[j][0]);
            p[j][1] = f2tf_f(p01 * er[j][1]);
            p[j][2] = f2tf_f(p10 * er[j][2]);
            p[j][3] = f2tf_f(p11 * er[j][3]);
        }

        // --- O[n][dd] += P * V ---
        #pragma unroll
        for (int kk = 0; kk < 8; kk++) {
            uint32_t a[4] = { __float_as_uint(p[kk][0]), __float_as_uint(p[kk][2]),
                              __float_as_uint(p[kk][1]), __float_as_uint(p[kk][3]) };
            #pragma unroll
            for (int jd = 0; jd < 8; jd++) {
                uint32_t b0 = __float_as_uint(Vs[(8 * jd + g) * VST + 8 * kk + tc]);
                uint32_t b1 = __float_as_uint(Vs[(8 * jd + g) * VST + 8 * kk + tc + 4]);
                mma_tf32(o[jd], a, b0, b1);
            }
        }

        __syncthreads();
        int tn = t + 2;
        if (tn < t0 + HALF_TILES) issueKV(tn * 64, st);
        else                      cpa_commit();
    }

    // --- epilogue: quad-reduce partial Z, store partial O (unnormalized) ---
    Z0 += __shfl_xor_sync(0xffffffffu, Z0, 1);
    Z0 += __shfl_xor_sync(0xffffffffu, Z0, 2);
    Z1 += __shfl_xor_sync(0xffffffffu, Z1, 1);
    Z1 += __shfl_xor_sync(0xffffffffu, Z1, 2);
    if (tc == 0) {
        float* zp = Pz + ((size_t)b * Hc + h) * Nc + n0 + nw;
        zp[g]     = Z0;
        zp[g + 8] = Z1;
    }

    #pragma unroll
    for (int jd = 0; jd < 8; jd++) {
        int dd0 = 8 * jd + 2 * tc;
        int dd1 = dd0 + 1;
        float* m0p = Po + ((size_t)b * Dc + dd0 * 4 + h) * Nc + n0 + nw;
        float* m1p = Po + ((size_t)b * Dc + dd1 * 4 + h) * Nc + n0 + nw;
        m0p[g]     = o[jd][0];
        m1p[g]     = o[jd][1];
        m0p[g + 8] = o[jd][2];
        m1p[g + 8] = o[jd][3];
    }
}

// ---------------------------------------------------------------------------
// Combine split-K partials: msg = round_tf32((O0+O1)/(Z0+Z1)).
// ---------------------------------------------------------------------------
__global__ void __launch_bounds__(256)
k_combine(const float4* __restrict__ po0, const float4* __restrict__ po1,
          const float* __restrict__ pz0, const float* __restrict__ pz1,
          float4* __restrict__ msg)
{
    int i = blockIdx.x * blockDim.x + threadIdx.x;   // < Bc*Dc*Nc/4
    int n4 = i & (Nc / 4 - 1);
    int ch = (i >> 9) & (Dc - 1);
    int b  = i >> 17;
    int h  = ch & 3;
    size_t zoff = ((size_t)b * Hc + h) * Nc + n4 * 4;
    float4 za = *(const float4*)(pz0 + zoff);
    float4 zb = *(const float4*)(pz1 + zoff);
    float4 a = po0[i], c = po1[i];
    float4 r;
    r.x = f2tf_f((a.x + c.x) / (za.x + zb.x));
    r.y = f2tf_f((a.y + c.y) / (za.y + zb.y));
    r.z = f2tf_f((a.z + c.z) / (za.z + zb.z));
    r.w = f2tf_f((a.w + c.w) / (za.w + zb.w));
    msg[i] = r;
}

// ---------------------------------------------------------------------------
// Launch
// ---------------------------------------------------------------------------
extern "C" void kernel_launch(void* const* d_in, const int* in_sizes, int n_in,
                              void* d_out, int out_size)
{
    const float* x    = (const float*)d_in[0];
    const float* src  = (const float*)d_in[1];
    const float* edge = (const float*)d_in[2];
    const float* Wq = (const float*)d_in[3];  const float* bq = (const float*)d_in[4];
    const float* Wk = (const float*)d_in[5];  const float* bk = (const float*)d_in[6];
    const float* Wv = (const float*)d_in[7];  const float* bv = (const float*)d_in[8];
    const float* Wm = (const float*)d_in[9];  const float* bm = (const float*)d_in[10];
    const float* W1 = (const float*)d_in[11]; const float* b1 = (const float*)d_in[12];
    const float* W2 = (const float*)d_in[13]; const float* b2 = (const float*)d_in[14];

    float *q, *k, *v, *msg, *message, *h1, *po, *pz;
    float *rx, *rs, *rWq, *rWk, *rWv, *rWm, *rW1, *rW2;
    cudaGetSymbolAddress((void**)&q,       g_q);
    cudaGetSymbolAddress((void**)&k,       g_k);
    cudaGetSymbolAddress((void**)&v,       g_v);
    cudaGetSymbolAddress((void**)&msg,     g_msg);
    cudaGetSymbolAddress((void**)&message, g_message);
    cudaGetSymbolAddress((void**)&h1,      g_h1);
    cudaGetSymbolAddress((void**)&po,      g_po);
    cudaGetSymbolAddress((void**)&pz,      g_pz);
    cudaGetSymbolAddress((void**)&rx,      g_rx);
    cudaGetSymbolAddress((void**)&rs,      g_rs);
    cudaGetSymbolAddress((void**)&rWq,     g_rWq);
    cudaGetSymbolAddress((void**)&rWk,     g_rWk);
    cudaGetSymbolAddress((void**)&rWv,     g_rWv);
    cudaGetSymbolAddress((void**)&rWm,     g_rWm);
    cudaGetSymbolAddress((void**)&rW1,     g_rW1);
    cudaGetSymbolAddress((void**)&rW2,     g_rW2);

    cudaFuncSetAttribute(k_flash, cudaFuncAttributeMaxDynamicSharedMemorySize,
                         FLASH_SMEM_BYTES);
    cudaFuncSetAttribute(k_conv_mma, cudaFuncAttributeMaxDynamicSharedMemorySize,
                         CONV_SMEM_BYTES);
    cudaFuncSetAttribute(k_qkv_mma, cudaFuncAttributeMaxDynamicSharedMemorySize,
                         CONV_SMEM_BYTES);

    // single fused tf32 pre-round (x, src, all weights)
    k_round_all<<<4736, 256>>>(
        (const float4*)x,  (const float4*)src,
        (const float4*)Wq, (const float4*)Wk,
        (const float4*)Wv, (const float4*)Wm,
        (const float4*)W1, (const float4*)W2,
        (float4*)rx,  (float4*)rs,
        (float4*)rWq, (float4*)rWk,
        (float4*)rWv, (float4*)rWm,
        (float4*)rW1, (float4*)rW2);

    // fused Q/K/V projections
    k_qkv_mma<<<dim3(Nc / 128, Dc / 64, Bc * 3), 256, CONV_SMEM_BYTES>>>(
        rWq, bq, rWk, bk, rWv, bv, rx, rs, q, k, v);

    // fused attention, split-K halves -> partials
    k_flash<<<dim3(Nc / 64, Bc * Hc, 2), 128, FLASH_SMEM_BYTES>>>(
        q, k, v, edge, po, pz);

    // combine partials -> msg (tf32-rounded for Wm's cp.async)
    k_combine<<<2048, 256>>>(
        (const float4*)po, (const float4*)(po + OSZ), pz, pz + ZSZ, (float4*)msg);

    // merge heads
    k_conv_mma<<<dim3(Nc / 128, Dc / 64, Bc), 256, CONV_SMEM_BYTES>>>(
        rWm, bm, msg, nullptr, message, Dc, Dc, 0, 0, 1);

    // MLP on concat([x, message])
    k_conv_mma<<<dim3(Nc / 128, 2 * Dc / 64, Bc), 256, CONV_SMEM_BYTES>>>(
        rW1, b1, rx, message, h1, 2 * Dc, Dc, Dc, 1, 1);
    k_conv_mma<<<dim3(Nc / 128, Dc / 64, Bc), 256, CONV_SMEM_BYTES>>>(
        rW2, b2, h1, nullptr, (float*)d_out, Dc, 2 * Dc, 0, 0, 0);
}